// round 1
// baseline (speedup 1.0000x reference)
#include <cuda_runtime.h>

// ---------------------------------------------------------------------------
// DSConv2d: offset conv (3x3, 128->18) + deformable conv (3x3, 128->128)
// B=16, C1=C2=128, H=W=80, K=3, PAD=1, STRIDE=1, fp32.
// ---------------------------------------------------------------------------

#define Hh 80
#define Ww 80
#define HW 6400
#define C1 128
#define C2 128
#define BATCH 16
#define OFFC 18   // 2*K*K offset channels

// scratch for offset conv output (no cudaMalloc allowed)
static __device__ float g_offset[BATCH * OFFC * HW];  // 7.37 MB

// ============================================================================
// Kernel 1: offset conv. 16x16 output tile per block, all 18 channels.
// C chunked by 16. xs tile + transposed weights in static smem.
// ============================================================================
#define OT 16
#define OCC 16

__global__ __launch_bounds__(256) void offset_conv_kernel(
    const float* __restrict__ x,
    const float* __restrict__ ow,   // [18][128][3][3]
    const float* __restrict__ ob)   // [18]
{
    __shared__ float xs[OCC][18][18];        // input tile with halo
    __shared__ float ws[OCC * 9][20];        // [k=(c,tap)][oc padded 18->20]

    const int b   = blockIdx.z;
    const int by0 = blockIdx.y * OT;
    const int bx0 = blockIdx.x * OT;
    const int t   = threadIdx.x;
    const int tx  = t & 15;
    const int ty  = t >> 4;

    float acc[18];
#pragma unroll
    for (int i = 0; i < 18; i++) acc[i] = 0.f;

    for (int cb = 0; cb < C1; cb += OCC) {
        __syncthreads();
        // ---- fill xs: OCC x 18 x 18 (zero-padded halo) ----
        for (int i = t; i < OCC * 18 * 18; i += 256) {
            int c   = i / 324;
            int rem = i - c * 324;
            int r   = rem / 18;
            int col = rem - r * 18;
            int y   = by0 - 1 + r;
            int xx  = bx0 - 1 + col;
            float v = 0.f;
            if (y >= 0 && y < Hh && xx >= 0 && xx < Ww)
                v = x[(b * C1 + cb + c) * HW + y * Ww + xx];
            xs[c][r][col] = v;
        }
        // ---- fill ws (transpose to [k][oc]) ----
        // source: ow[oc*1152 + cb*9 + k], k in [0,144) contiguous per oc
        for (int i = t; i < 18 * 36; i += 256) {
            int oc = i / 36;
            int q  = i - oc * 36;
            float4 v = *reinterpret_cast<const float4*>(ow + oc * (C1 * 9) + cb * 9 + q * 4);
            int k = q * 4;
            ws[k + 0][oc] = v.x;
            ws[k + 1][oc] = v.y;
            ws[k + 2][oc] = v.z;
            ws[k + 3][oc] = v.w;
        }
        __syncthreads();

        // ---- compute ----
#pragma unroll 1
        for (int c = 0; c < OCC; c++) {
#pragma unroll
            for (int tap = 0; tap < 9; tap++) {
                const int ki = tap / 3;
                const int kj = tap % 3;
                float xv = xs[c][ty + ki][tx + kj];
                const float* wp = &ws[c * 9 + tap][0];
                float wreg[18];
                float4 w0 = *reinterpret_cast<const float4*>(wp);
                float4 w1 = *reinterpret_cast<const float4*>(wp + 4);
                float4 w2 = *reinterpret_cast<const float4*>(wp + 8);
                float4 w3 = *reinterpret_cast<const float4*>(wp + 12);
                wreg[0] = w0.x;  wreg[1] = w0.y;  wreg[2] = w0.z;  wreg[3] = w0.w;
                wreg[4] = w1.x;  wreg[5] = w1.y;  wreg[6] = w1.z;  wreg[7] = w1.w;
                wreg[8] = w2.x;  wreg[9] = w2.y;  wreg[10] = w2.z; wreg[11] = w2.w;
                wreg[12] = w3.x; wreg[13] = w3.y; wreg[14] = w3.z; wreg[15] = w3.w;
                wreg[16] = wp[16]; wreg[17] = wp[17];
#pragma unroll
                for (int j = 0; j < 18; j++)
                    acc[j] = fmaf(xv, wreg[j], acc[j]);
            }
        }
    }

    const int pix = (by0 + ty) * Ww + bx0 + tx;
#pragma unroll
    for (int ch = 0; ch < 18; ch++)
        g_offset[(b * OFFC + ch) * HW + pix] = acc[ch] + ob[ch];
}

// ============================================================================
// Kernel 2: deformable conv as implicit GEMM.
// Block tile: M=64 pixels x N=128 out-channels. K=1152 chunked by 72 (8c x 9tap).
// Bilinear sampling metadata precomputed once per block in smem.
// ============================================================================
#define MT 64
#define CCH 8
#define KC (CCH * 9)  // 72

__global__ __launch_bounds__(256) void deform_conv_kernel(
    const float* __restrict__ x,
    const float* __restrict__ wgt,   // [128][128][3][3]
    const float* __restrict__ bias,  // [128]
    float* __restrict__ out)
{
    extern __shared__ float sm[];
    float* Ws = sm;                           // [128][72]
    float* As = Ws + C2 * KC;                 // [72][64]
    float* mw = As + KC * MT;                 // [4][9*64] corner weights
    int*   mo = reinterpret_cast<int*>(mw + 4 * 576);  // [4][9*64] corner idx

    const int b    = blockIdx.y;
    const int pix0 = blockIdx.x * MT;
    const int t    = threadIdx.x;

    // ---- metadata: 64 px x 9 taps -> 4 corner (index, masked weight) ----
    for (int i = t; i < 576; i += 256) {
        const int p   = i >> 6;
        const int px  = i & 63;
        const int pix = pix0 + px;
        const int ho  = pix / Ww;
        const int wo  = pix - ho * Ww;
        const int ki  = p / 3;
        const int kj  = p % 3;
        float dy = g_offset[(b * OFFC + 2 * p) * HW + pix];
        float dx = g_offset[(b * OFFC + 2 * p + 1) * HW + pix];
        float py  = (float)(ho - 1 + ki) + dy;
        float pxx = (float)(wo - 1 + kj) + dx;
        float y0 = floorf(py);
        float x0 = floorf(pxx);
        float wy1 = py - y0, wy0 = 1.f - wy1;
        float wx1 = pxx - x0, wx0 = 1.f - wx1;
        float y1 = y0 + 1.f, x1 = x0 + 1.f;

        float yc[2] = {y0, y1};
        float xc[2] = {x0, x1};
        float wy[2] = {wy0, wy1};
        float wx[2] = {wx0, wx1};
#pragma unroll
        for (int cy = 0; cy < 2; cy++) {
#pragma unroll
            for (int cx = 0; cx < 2; cx++) {
                const int cr = cy * 2 + cx;
                bool valid = (yc[cy] >= 0.f) && (yc[cy] < (float)Hh) &&
                             (xc[cx] >= 0.f) && (xc[cx] < (float)Ww);
                int iy = (int)fminf(fmaxf(yc[cy], 0.f), (float)(Hh - 1));
                int ix = (int)fminf(fmaxf(xc[cx], 0.f), (float)(Ww - 1));
                mw[cr * 576 + i] = valid ? (wy[cy] * wx[cx]) : 0.f;
                mo[cr * 576 + i] = iy * Ww + ix;
            }
        }
    }
    __syncthreads();

    const int mi = t & 15;   // pixel group (4 px each)
    const int ni = t >> 4;   // oc group (8 oc each)

    float acc[4][8];
#pragma unroll
    for (int m = 0; m < 4; m++)
#pragma unroll
        for (int j = 0; j < 8; j++) acc[m][j] = 0.f;

#pragma unroll 1
    for (int cb = 0; cb < C1; cb += CCH) {
        __syncthreads();
        // ---- fill Ws: [oc][72], contiguous copy from gmem ----
        for (int i = t; i < C2 * 18; i += 256) {
            int oc = i / 18;
            int q  = i - oc * 18;
            float4 v = *reinterpret_cast<const float4*>(wgt + oc * (C1 * 9) + cb * 9 + q * 4);
            *reinterpret_cast<float4*>(Ws + oc * KC + q * 4) = v;
        }
        // ---- fill As: [k=(ci,p)][px] via bilinear gather ----
        for (int ii = t; ii < 576; ii += 256) {
            const int p  = ii >> 6;
            const int px = ii & 63;
            const float w0 = mw[0 * 576 + ii];
            const float w1 = mw[1 * 576 + ii];
            const float w2 = mw[2 * 576 + ii];
            const float w3 = mw[3 * 576 + ii];
            const int o0 = mo[0 * 576 + ii];
            const int o1 = mo[1 * 576 + ii];
            const int o2 = mo[2 * 576 + ii];
            const int o3 = mo[3 * 576 + ii];
#pragma unroll
            for (int ci = 0; ci < CCH; ci++) {
                const float* xp = x + (b * C1 + cb + ci) * HW;
                float v = w0 * xp[o0];
                v = fmaf(w1, xp[o1], v);
                v = fmaf(w2, xp[o2], v);
                v = fmaf(w3, xp[o3], v);
                As[(ci * 9 + p) * MT + px] = v;
            }
        }
        __syncthreads();

        // ---- GEMM: 72 k-steps, 4px x 8oc register tile ----
        const float4* As4 = reinterpret_cast<const float4*>(As);
        const float4* Ws4 = reinterpret_cast<const float4*>(Ws);
#pragma unroll 2
        for (int k4 = 0; k4 < KC / 4; k4++) {
            float wr[8][4];
#pragma unroll
            for (int j = 0; j < 8; j++) {
                float4 w = Ws4[(ni * 8 + j) * (KC / 4) + k4];
                wr[j][0] = w.x; wr[j][1] = w.y; wr[j][2] = w.z; wr[j][3] = w.w;
            }
#pragma unroll
            for (int u = 0; u < 4; u++) {
                float4 a = As4[(k4 * 4 + u) * (MT / 4) + mi];
#pragma unroll
                for (int j = 0; j < 8; j++) {
                    acc[0][j] = fmaf(a.x, wr[j][u], acc[0][j]);
                    acc[1][j] = fmaf(a.y, wr[j][u], acc[1][j]);
                    acc[2][j] = fmaf(a.z, wr[j][u], acc[2][j]);
                    acc[3][j] = fmaf(a.w, wr[j][u], acc[3][j]);
                }
            }
        }
    }

    // ---- epilogue ----
#pragma unroll
    for (int j = 0; j < 8; j++) {
        const int oc = ni * 8 + j;
        const float bv = bias[oc];
        float4 o;
        o.x = acc[0][j] + bv;
        o.y = acc[1][j] + bv;
        o.z = acc[2][j] + bv;
        o.w = acc[3][j] + bv;
        *reinterpret_cast<float4*>(out + (b * C2 + oc) * HW + pix0 + mi * 4) = o;
    }
}

// ============================================================================
extern "C" void kernel_launch(void* const* d_in, const int* in_sizes, int n_in,
                              void* d_out, int out_size) {
    const float* x    = (const float*)d_in[0];
    const float* ow   = (const float*)d_in[1];
    const float* ob   = (const float*)d_in[2];
    const float* wgt  = (const float*)d_in[3];
    const float* bias = (const float*)d_in[4];
    float* out = (float*)d_out;

    // offset conv
    dim3 g1(Ww / OT, Hh / OT, BATCH);
    offset_conv_kernel<<<g1, 256>>>(x, ow, ob);

    // deformable conv
    const size_t smem_bytes =
        (size_t)(C2 * KC + KC * MT + 4 * 576) * sizeof(float) +
        (size_t)(4 * 576) * sizeof(int);  // 73728 bytes
    cudaFuncSetAttribute(deform_conv_kernel,
                         cudaFuncAttributeMaxDynamicSharedMemorySize,
                         (int)smem_bytes);
    dim3 g2(HW / MT, BATCH);
    deform_conv_kernel<<<g2, 256, smem_bytes>>>(x, wgt, bias, out);
}

// round 3
// speedup vs baseline: 1.2339x; 1.2339x over previous
#include <cuda_runtime.h>
#include <cuda_bf16.h>
#include <mma.h>
#include <cstdint>

using namespace nvcuda;

// ---------------------------------------------------------------------------
// DSConv2d: offset conv (3x3, 128->18) + deformable conv (3x3, 128->128)
// B=16, C1=C2=128, H=W=80, fp32.
// Deform conv: implicit GEMM on tensor cores via WMMA bf16 3-term split.
// ---------------------------------------------------------------------------

#define Hh 80
#define Ww 80
#define HW 6400
#define C1 128
#define C2 128
#define BATCH 16
#define OFFC 18

static __device__ float g_offset[BATCH * OFFC * HW];   // 7.37 MB scratch
static __device__ float g_wT[9 * 128 * 128];           // wT[tap][oc][c]

// ============================================================================
// Kernel 0: one-time weight transpose  wT[tap][oc][c] = wgt[oc][c][tap]
// ============================================================================
__global__ __launch_bounds__(256) void transpose_w_kernel(
    const float* __restrict__ wgt)
{
    int i = blockIdx.x * 256 + threadIdx.x;   // i = (tap*128 + oc)*128 + c
    if (i < 9 * 128 * 128) {
        int c    = i & 127;
        int rest = i >> 7;
        int oc   = rest & 127;
        int tap  = rest >> 7;
        g_wT[i] = wgt[(oc * 128 + c) * 9 + tap];
    }
}

// ============================================================================
// Kernel 1: offset conv (verified numerics, unchanged)
// ============================================================================
#define OT 16
#define OCC 16

__global__ __launch_bounds__(256) void offset_conv_kernel(
    const float* __restrict__ x,
    const float* __restrict__ ow,
    const float* __restrict__ ob)
{
    __shared__ float xs[OCC][18][18];
    __shared__ float ws[OCC * 9][20];

    const int b   = blockIdx.z;
    const int by0 = blockIdx.y * OT;
    const int bx0 = blockIdx.x * OT;
    const int t   = threadIdx.x;
    const int tx  = t & 15;
    const int ty  = t >> 4;

    float acc[18];
#pragma unroll
    for (int i = 0; i < 18; i++) acc[i] = 0.f;

    for (int cb = 0; cb < C1; cb += OCC) {
        __syncthreads();
        for (int i = t; i < OCC * 18 * 18; i += 256) {
            int c   = i / 324;
            int rem = i - c * 324;
            int r   = rem / 18;
            int col = rem - r * 18;
            int y   = by0 - 1 + r;
            int xx  = bx0 - 1 + col;
            float v = 0.f;
            if (y >= 0 && y < Hh && xx >= 0 && xx < Ww)
                v = x[(b * C1 + cb + c) * HW + y * Ww + xx];
            xs[c][r][col] = v;
        }
        for (int i = t; i < 18 * 36; i += 256) {
            int oc = i / 36;
            int q  = i - oc * 36;
            float4 v = *reinterpret_cast<const float4*>(ow + oc * (C1 * 9) + cb * 9 + q * 4);
            int k = q * 4;
            ws[k + 0][oc] = v.x;
            ws[k + 1][oc] = v.y;
            ws[k + 2][oc] = v.z;
            ws[k + 3][oc] = v.w;
        }
        __syncthreads();

#pragma unroll 1
        for (int c = 0; c < OCC; c++) {
#pragma unroll
            for (int tap = 0; tap < 9; tap++) {
                const int ki = tap / 3;
                const int kj = tap % 3;
                float xv = xs[c][ty + ki][tx + kj];
                const float* wp = &ws[c * 9 + tap][0];
                float wreg[18];
                float4 w0 = *reinterpret_cast<const float4*>(wp);
                float4 w1 = *reinterpret_cast<const float4*>(wp + 4);
                float4 w2 = *reinterpret_cast<const float4*>(wp + 8);
                float4 w3 = *reinterpret_cast<const float4*>(wp + 12);
                wreg[0] = w0.x;  wreg[1] = w0.y;  wreg[2] = w0.z;  wreg[3] = w0.w;
                wreg[4] = w1.x;  wreg[5] = w1.y;  wreg[6] = w1.z;  wreg[7] = w1.w;
                wreg[8] = w2.x;  wreg[9] = w2.y;  wreg[10] = w2.z; wreg[11] = w2.w;
                wreg[12] = w3.x; wreg[13] = w3.y; wreg[14] = w3.z; wreg[15] = w3.w;
                wreg[16] = wp[16]; wreg[17] = wp[17];
#pragma unroll
                for (int j = 0; j < 18; j++)
                    acc[j] = fmaf(xv, wreg[j], acc[j]);
            }
        }
    }

    const int pix = (by0 + ty) * Ww + bx0 + tx;
#pragma unroll
    for (int ch = 0; ch < 18; ch++)
        g_offset[(b * OFFC + ch) * HW + pix] = acc[ch] + ob[ch];
}

// ============================================================================
// Kernel 2: deformable conv, WMMA bf16 3-term split implicit GEMM.
// Block = 128 px x 128 oc, 256 threads = 8 warps (2 m-groups x 4 n-groups).
// Per tap: gather+split A[128][128] (hi/lo bf16), load+split B, then each warp
// does 8 k-chunks x (4m x 2n) x 3 terms of wmma 16x16x16.
// ============================================================================
#define LDA 136   // bf16 elements per smem row (128 + 8 pad)
#define LDO 132   // f32 elements per s_out row

// smem byte offsets
#define SMO_BIAS 0
#define SMO_MW   512
#define SMO_MI   2560
#define SMO_AH   4608
#define SMO_AL   (SMO_AH + 128 * LDA * 2)   // +34816
#define SMO_BH   (SMO_AL + 128 * LDA * 2)
#define SMO_BL   (SMO_BH + 128 * LDA * 2)
#define SMEM_TOTAL_D (SMO_BL + 128 * LDA * 2)  // 143872

__device__ __forceinline__ uint32_t split_pack(float va, float vb,
                                               uint32_t& lo_pair) {
    __nv_bfloat16 ha = __float2bfloat16_rn(va);
    __nv_bfloat16 hb = __float2bfloat16_rn(vb);
    __nv_bfloat16 la = __float2bfloat16_rn(va - __bfloat162float(ha));
    __nv_bfloat16 lb = __float2bfloat16_rn(vb - __bfloat162float(hb));
    lo_pair = ((uint32_t)__bfloat16_as_ushort(lb) << 16) |
              (uint32_t)__bfloat16_as_ushort(la);
    return ((uint32_t)__bfloat16_as_ushort(hb) << 16) |
           (uint32_t)__bfloat16_as_ushort(ha);
}

__global__ __launch_bounds__(256, 1)
void deform_wmma_kernel(const float* __restrict__ x,
                        const float* __restrict__ bias,
                        float* __restrict__ out)
{
    extern __shared__ char smem[];
    float* s_bias = reinterpret_cast<float*>(smem + SMO_BIAS);
    float* s_mw   = reinterpret_cast<float*>(smem + SMO_MW);
    int*   s_mi   = reinterpret_cast<int*>(smem + SMO_MI);
    __nv_bfloat16* Ah = reinterpret_cast<__nv_bfloat16*>(smem + SMO_AH);
    __nv_bfloat16* Al = reinterpret_cast<__nv_bfloat16*>(smem + SMO_AL);
    __nv_bfloat16* Bh = reinterpret_cast<__nv_bfloat16*>(smem + SMO_BH);
    __nv_bfloat16* Bl = reinterpret_cast<__nv_bfloat16*>(smem + SMO_BL);
    float* s_out = reinterpret_cast<float*>(smem + SMO_AH);  // reuse after MMA

    const int t    = threadIdx.x;
    const int wid  = t >> 5;
    const int b    = blockIdx.y;
    const int pix0 = blockIdx.x * 128;
    const int wm   = wid & 1;    // 2 m-groups of 64 px
    const int wn   = wid >> 1;   // 4 n-groups of 32 oc

    wmma::fragment<wmma::accumulator, 16, 16, 16, float> acc[4][2];
#pragma unroll
    for (int mt = 0; mt < 4; mt++)
#pragma unroll
        for (int nt = 0; nt < 2; nt++)
            wmma::fill_fragment(acc[mt][nt], 0.f);

    if (t < 128) s_bias[t] = bias[t];

#pragma unroll 1
    for (int tap = 0; tap < 9; tap++) {
        // ---- bilinear metadata for this tap's 128 px ----
        if (t < 128) {
            const int pix = pix0 + t;
            const int ho  = pix / Ww;
            const int wo  = pix - ho * Ww;
            const int ki  = tap / 3;
            const int kj  = tap % 3;
            float dy = g_offset[(b * OFFC + 2 * tap) * HW + pix];
            float dx = g_offset[(b * OFFC + 2 * tap + 1) * HW + pix];
            float py  = (float)(ho - 1 + ki) + dy;
            float pxx = (float)(wo - 1 + kj) + dx;
            float y0 = floorf(py);
            float x0 = floorf(pxx);
            float wy1 = py - y0, wy0 = 1.f - wy1;
            float wx1 = pxx - x0, wx0 = 1.f - wx1;
#pragma unroll
            for (int cy = 0; cy < 2; cy++) {
#pragma unroll
                for (int cx = 0; cx < 2; cx++) {
                    float yc = y0 + (float)cy;
                    float xc = x0 + (float)cx;
                    bool valid = (yc >= 0.f) && (yc < (float)Hh) &&
                                 (xc >= 0.f) && (xc < (float)Ww);
                    int iy = (int)fminf(fmaxf(yc, 0.f), (float)(Hh - 1));
                    int ix = (int)fminf(fmaxf(xc, 0.f), (float)(Ww - 1));
                    int cr = cy * 2 + cx;
                    s_mw[cr * 128 + t] = valid ? ((cy ? wy1 : wy0) * (cx ? wx1 : wx0)) : 0.f;
                    s_mi[cr * 128 + t] = iy * Ww + ix;
                }
            }
        }
        __syncthreads();   // meta ready; prior-iter frag loads already complete

        // ---- A: gather + bilinear + bf16 split. thread -> (px, 64 channels) ----
        {
            const int px = t & 127;
            const int c0 = (t >> 7) * 64;
            const float w0 = s_mw[0 * 128 + px], w1 = s_mw[1 * 128 + px];
            const float w2 = s_mw[2 * 128 + px], w3 = s_mw[3 * 128 + px];
            const int o0 = s_mi[0 * 128 + px], o1 = s_mi[1 * 128 + px];
            const int o2 = s_mi[2 * 128 + px], o3 = s_mi[3 * 128 + px];
            const float* xb = x + (size_t)(b * C1 + c0) * HW;
            uint32_t* ah_row = reinterpret_cast<uint32_t*>(Ah + px * LDA + c0);
            uint32_t* al_row = reinterpret_cast<uint32_t*>(Al + px * LDA + c0);
#pragma unroll 4
            for (int j = 0; j < 32; j++) {
                const float* xp0 = xb + (size_t)(2 * j) * HW;
                const float* xp1 = xp0 + HW;
                float va = w0 * xp0[o0];
                va = fmaf(w1, xp0[o1], va);
                va = fmaf(w2, xp0[o2], va);
                va = fmaf(w3, xp0[o3], va);
                float vb = w0 * xp1[o0];
                vb = fmaf(w1, xp1[o1], vb);
                vb = fmaf(w2, xp1[o2], vb);
                vb = fmaf(w3, xp1[o3], vb);
                uint32_t lo;
                uint32_t hi = split_pack(va, vb, lo);
                ah_row[j] = hi;
                al_row[j] = lo;
            }
        }
        // ---- B: load wT[tap][oc][c] + bf16 split ----
        {
#pragma unroll 4
            for (int j = 0; j < 16; j++) {
                int idx = t + 256 * j;          // 4096 = 128 oc x 32 c-groups
                int oc  = idx >> 5;
                int cg  = (idx & 31) * 4;
                float4 v = *reinterpret_cast<const float4*>(
                    g_wT + (size_t)(tap * 128 + oc) * 128 + cg);
                uint32_t lo0, lo1;
                uint32_t hi0 = split_pack(v.x, v.y, lo0);
                uint32_t hi1 = split_pack(v.z, v.w, lo1);
                uint2* bh = reinterpret_cast<uint2*>(Bh + oc * LDA + cg);
                uint2* bl = reinterpret_cast<uint2*>(Bl + oc * LDA + cg);
                *bh = make_uint2(hi0, hi1);
                *bl = make_uint2(lo0, lo1);
            }
        }
        __syncthreads();

        // ---- MMA: 8 k-chunks x 3 terms x (4m x 2n) ----
        const int m0 = wm * 64;
        const int n0 = wn * 32;
#pragma unroll 1
        for (int kc = 0; kc < 8; kc++) {
            const int k0 = kc * 16;
            wmma::fragment<wmma::matrix_a, 16, 16, 16, __nv_bfloat16, wmma::row_major> ah[4], al[4];
            wmma::fragment<wmma::matrix_b, 16, 16, 16, __nv_bfloat16, wmma::col_major> bh[2], bl[2];
#pragma unroll
            for (int mt = 0; mt < 4; mt++) {
                wmma::load_matrix_sync(ah[mt], Ah + (m0 + mt * 16) * LDA + k0, LDA);
                wmma::load_matrix_sync(al[mt], Al + (m0 + mt * 16) * LDA + k0, LDA);
            }
#pragma unroll
            for (int nt = 0; nt < 2; nt++) {
                wmma::load_matrix_sync(bh[nt], Bh + (n0 + nt * 16) * LDA + k0, LDA);
                wmma::load_matrix_sync(bl[nt], Bl + (n0 + nt * 16) * LDA + k0, LDA);
            }
#pragma unroll
            for (int mt = 0; mt < 4; mt++) {
#pragma unroll
                for (int nt = 0; nt < 2; nt++) {
                    wmma::mma_sync(acc[mt][nt], ah[mt], bh[nt], acc[mt][nt]);
                    wmma::mma_sync(acc[mt][nt], ah[mt], bl[nt], acc[mt][nt]);
                    wmma::mma_sync(acc[mt][nt], al[mt], bh[nt], acc[mt][nt]);
                }
            }
        }
    }

    // ---- epilogue: accum -> smem [px][oc], then coalesced gmem store ----
    __syncthreads();
#pragma unroll
    for (int mt = 0; mt < 4; mt++)
#pragma unroll
        for (int nt = 0; nt < 2; nt++)
            wmma::store_matrix_sync(
                s_out + (wm * 64 + mt * 16) * LDO + wn * 32 + nt * 16,
                acc[mt][nt], LDO, wmma::mem_row_major);
    __syncthreads();

#pragma unroll 4
    for (int j = 0; j < 64; j++) {
        int i  = t + 256 * j;   // 16384 outputs
        int oc = i >> 7;
        int px = i & 127;
        out[(size_t)(b * C2 + oc) * HW + pix0 + px] =
            s_out[px * LDO + oc] + s_bias[oc];
    }
}

// ============================================================================
extern "C" void kernel_launch(void* const* d_in, const int* in_sizes, int n_in,
                              void* d_out, int out_size) {
    const float* x    = (const float*)d_in[0];
    const float* ow   = (const float*)d_in[1];
    const float* ob   = (const float*)d_in[2];
    const float* wgt  = (const float*)d_in[3];
    const float* bias = (const float*)d_in[4];
    float* out = (float*)d_out;

    transpose_w_kernel<<<(9 * 128 * 128 + 255) / 256, 256>>>(wgt);

    dim3 g1(Ww / OT, Hh / OT, BATCH);
    offset_conv_kernel<<<g1, 256>>>(x, ow, ob);

    cudaFuncSetAttribute(deform_wmma_kernel,
                         cudaFuncAttributeMaxDynamicSharedMemorySize,
                         SMEM_TOTAL_D);
    dim3 g2(HW / 128, BATCH);
    deform_wmma_kernel<<<g2, 256, SMEM_TOTAL_D>>>(x, bias, out);
}

// round 4
// speedup vs baseline: 1.3034x; 1.0563x over previous
#include <cuda_runtime.h>
#include <cuda_bf16.h>
#include <mma.h>
#include <cstdint>

using namespace nvcuda;

// ---------------------------------------------------------------------------
// DSConv2d: offset conv (3x3, 128->18) + deformable conv (3x3, 128->128)
// B=16, C1=C2=128, H=W=80, fp32.
// Deform conv: NHWC coalesced bilinear gather + WMMA bf16 3-term split GEMM.
// ---------------------------------------------------------------------------

#define Hh 80
#define Ww 80
#define HW 6400
#define C1 128
#define C2 128
#define BATCH 16
#define OFFC 18

static __device__ float g_offset[BATCH * OFFC * HW];           // 7.37 MB
static __device__ float g_xT[BATCH * HW * C1];                 // 52.4 MB NHWC
static __device__ __nv_bfloat16 g_wBh[9 * 128 * 128];          // wT hi [tap][oc][c]
static __device__ __nv_bfloat16 g_wBl[9 * 128 * 128];          // wT lo

// ============================================================================
// Kernel 0a: NCHW -> NHWC transform of x (smem-tiled transpose)
// ============================================================================
__global__ __launch_bounds__(256) void nhwc_kernel(const float* __restrict__ x)
{
    __shared__ float tile[128][81];
    const int h = blockIdx.x;
    const int b = blockIdx.y;
    const int t = threadIdx.x;

    // load: rows = channel, cols = w  (coalesced 320B rows)
    for (int idx = t; idx < 128 * 80; idx += 256) {
        int c = idx / 80;
        int w = idx - c * 80;
        tile[c][w] = x[((size_t)(b * C1 + c) * Hh + h) * Ww + w];
    }
    __syncthreads();
    // store: NHWC, coalesced 512B per w
    for (int idx = t; idx < 80 * 128; idx += 256) {
        int w = idx >> 7;
        int c = idx & 127;
        g_xT[((size_t)b * HW + h * Ww + w) * C1 + c] = tile[c][w];
    }
}

// ============================================================================
// Kernel 0b: weight transpose + bf16 hi/lo pre-split
//   g_wBh/l[(tap*128+oc)*128+c]  <-  split(wgt[oc][c][tap])
// ============================================================================
__global__ __launch_bounds__(256) void prep_w_kernel(const float* __restrict__ wgt)
{
    int i = blockIdx.x * 256 + threadIdx.x;
    if (i < 9 * 128 * 128) {
        int c    = i & 127;
        int rest = i >> 7;
        int oc   = rest & 127;
        int tap  = rest >> 7;
        float w = wgt[(oc * 128 + c) * 9 + tap];
        __nv_bfloat16 hi = __float2bfloat16_rn(w);
        __nv_bfloat16 lo = __float2bfloat16_rn(w - __bfloat162float(hi));
        g_wBh[i] = hi;
        g_wBl[i] = lo;
    }
}

// ============================================================================
// Kernel 1: offset conv (verified numerics, unchanged)
// ============================================================================
#define OT 16
#define OCC 16

__global__ __launch_bounds__(256) void offset_conv_kernel(
    const float* __restrict__ x,
    const float* __restrict__ ow,
    const float* __restrict__ ob)
{
    __shared__ float xs[OCC][18][18];
    __shared__ float ws[OCC * 9][20];

    const int b   = blockIdx.z;
    const int by0 = blockIdx.y * OT;
    const int bx0 = blockIdx.x * OT;
    const int t   = threadIdx.x;
    const int tx  = t & 15;
    const int ty  = t >> 4;

    float acc[18];
#pragma unroll
    for (int i = 0; i < 18; i++) acc[i] = 0.f;

    for (int cb = 0; cb < C1; cb += OCC) {
        __syncthreads();
        for (int i = t; i < OCC * 18 * 18; i += 256) {
            int c   = i / 324;
            int rem = i - c * 324;
            int r   = rem / 18;
            int col = rem - r * 18;
            int y   = by0 - 1 + r;
            int xx  = bx0 - 1 + col;
            float v = 0.f;
            if (y >= 0 && y < Hh && xx >= 0 && xx < Ww)
                v = x[(b * C1 + cb + c) * HW + y * Ww + xx];
            xs[c][r][col] = v;
        }
        for (int i = t; i < 18 * 36; i += 256) {
            int oc = i / 36;
            int q  = i - oc * 36;
            float4 v = *reinterpret_cast<const float4*>(ow + oc * (C1 * 9) + cb * 9 + q * 4);
            int k = q * 4;
            ws[k + 0][oc] = v.x;
            ws[k + 1][oc] = v.y;
            ws[k + 2][oc] = v.z;
            ws[k + 3][oc] = v.w;
        }
        __syncthreads();

#pragma unroll 1
        for (int c = 0; c < OCC; c++) {
#pragma unroll
            for (int tap = 0; tap < 9; tap++) {
                const int ki = tap / 3;
                const int kj = tap % 3;
                float xv = xs[c][ty + ki][tx + kj];
                const float* wp = &ws[c * 9 + tap][0];
                float wreg[18];
                float4 w0 = *reinterpret_cast<const float4*>(wp);
                float4 w1 = *reinterpret_cast<const float4*>(wp + 4);
                float4 w2 = *reinterpret_cast<const float4*>(wp + 8);
                float4 w3 = *reinterpret_cast<const float4*>(wp + 12);
                wreg[0] = w0.x;  wreg[1] = w0.y;  wreg[2] = w0.z;  wreg[3] = w0.w;
                wreg[4] = w1.x;  wreg[5] = w1.y;  wreg[6] = w1.z;  wreg[7] = w1.w;
                wreg[8] = w2.x;  wreg[9] = w2.y;  wreg[10] = w2.z; wreg[11] = w2.w;
                wreg[12] = w3.x; wreg[13] = w3.y; wreg[14] = w3.z; wreg[15] = w3.w;
                wreg[16] = wp[16]; wreg[17] = wp[17];
#pragma unroll
                for (int j = 0; j < 18; j++)
                    acc[j] = fmaf(xv, wreg[j], acc[j]);
            }
        }
    }

    const int pix = (by0 + ty) * Ww + bx0 + tx;
#pragma unroll
    for (int ch = 0; ch < 18; ch++)
        g_offset[(b * OFFC + ch) * HW + pix] = acc[ch] + ob[ch];
}

// ============================================================================
// Kernel 2: deformable conv. NHWC gathers + WMMA bf16 3-term split.
// Block = 128 px x 128 oc, 256 threads = 8 warps (2 m-groups x 4 n-groups).
// ============================================================================
#define LDA 136   // bf16 elements per smem row
#define LDO 132   // f32 elements per s_out row

#define SMO_BIAS 0
#define SMO_MW   512
#define SMO_MI   2560
#define SMO_AH   4608
#define SMO_AL   (SMO_AH + 128 * LDA * 2)
#define SMO_BH   (SMO_AL + 128 * LDA * 2)
#define SMO_BL   (SMO_BH + 128 * LDA * 2)
#define SMEM_TOTAL_D (SMO_BL + 128 * LDA * 2)  // 143872

__device__ __forceinline__ uint32_t split_pack2(float va, float vb,
                                                uint32_t& lo_pair) {
    __nv_bfloat16 ha = __float2bfloat16_rn(va);
    __nv_bfloat16 hb = __float2bfloat16_rn(vb);
    __nv_bfloat16 la = __float2bfloat16_rn(va - __bfloat162float(ha));
    __nv_bfloat16 lb = __float2bfloat16_rn(vb - __bfloat162float(hb));
    lo_pair = ((uint32_t)__bfloat16_as_ushort(lb) << 16) |
              (uint32_t)__bfloat16_as_ushort(la);
    return ((uint32_t)__bfloat16_as_ushort(hb) << 16) |
           (uint32_t)__bfloat16_as_ushort(ha);
}

__global__ __launch_bounds__(256, 1)
void deform_wmma_kernel(const float* __restrict__ bias,
                        float* __restrict__ out)
{
    extern __shared__ char smem[];
    float* s_bias = reinterpret_cast<float*>(smem + SMO_BIAS);
    float* s_mw   = reinterpret_cast<float*>(smem + SMO_MW);
    int*   s_mi   = reinterpret_cast<int*>(smem + SMO_MI);
    __nv_bfloat16* Ah = reinterpret_cast<__nv_bfloat16*>(smem + SMO_AH);
    __nv_bfloat16* Al = reinterpret_cast<__nv_bfloat16*>(smem + SMO_AL);
    __nv_bfloat16* Bh = reinterpret_cast<__nv_bfloat16*>(smem + SMO_BH);
    __nv_bfloat16* Bl = reinterpret_cast<__nv_bfloat16*>(smem + SMO_BL);
    float* s_out = reinterpret_cast<float*>(smem + SMO_AH);  // reuse post-MMA

    const int t    = threadIdx.x;
    const int wid  = t >> 5;
    const int lane = t & 31;
    const int b    = blockIdx.y;
    const int pix0 = blockIdx.x * 128;
    const int wm   = wid & 1;
    const int wn   = wid >> 1;

    const float* xTb = g_xT + (size_t)b * HW * C1;

    wmma::fragment<wmma::accumulator, 16, 16, 16, float> acc[4][2];
#pragma unroll
    for (int mt = 0; mt < 4; mt++)
#pragma unroll
        for (int nt = 0; nt < 2; nt++)
            wmma::fill_fragment(acc[mt][nt], 0.f);

    if (t < 128) s_bias[t] = bias[t];

#pragma unroll 1
    for (int tap = 0; tap < 9; tap++) {
        // ---- bilinear metadata for this tap's 128 px ----
        if (t < 128) {
            const int pix = pix0 + t;
            const int ho  = pix / Ww;
            const int wo  = pix - ho * Ww;
            const int ki  = tap / 3;
            const int kj  = tap % 3;
            float dy = g_offset[(b * OFFC + 2 * tap) * HW + pix];
            float dx = g_offset[(b * OFFC + 2 * tap + 1) * HW + pix];
            float py  = (float)(ho - 1 + ki) + dy;
            float pxx = (float)(wo - 1 + kj) + dx;
            float y0 = floorf(py);
            float x0 = floorf(pxx);
            float wy1 = py - y0, wy0 = 1.f - wy1;
            float wx1 = pxx - x0, wx0 = 1.f - wx1;
#pragma unroll
            for (int cy = 0; cy < 2; cy++) {
#pragma unroll
                for (int cx = 0; cx < 2; cx++) {
                    float yc = y0 + (float)cy;
                    float xc = x0 + (float)cx;
                    bool valid = (yc >= 0.f) && (yc < (float)Hh) &&
                                 (xc >= 0.f) && (xc < (float)Ww);
                    int iy = (int)fminf(fmaxf(yc, 0.f), (float)(Hh - 1));
                    int ix = (int)fminf(fmaxf(xc, 0.f), (float)(Ww - 1));
                    int cr = cy * 2 + cx;
                    s_mw[cr * 128 + t] = valid ? ((cy ? wy1 : wy0) * (cx ? wx1 : wx0)) : 0.f;
                    s_mi[cr * 128 + t] = iy * Ww + ix;
                }
            }
        }
        __syncthreads();

        // ---- A: coalesced NHWC gather. warp -> 16 px, lane -> 4 channels ----
        {
            const int pxbase = wid * 16;
#pragma unroll 2
            for (int i = 0; i < 16; i++) {
                const int px = pxbase + i;
                const float w0 = s_mw[0 * 128 + px], w1 = s_mw[1 * 128 + px];
                const float w2 = s_mw[2 * 128 + px], w3 = s_mw[3 * 128 + px];
                const float4* p0 = reinterpret_cast<const float4*>(
                    xTb + (size_t)s_mi[0 * 128 + px] * C1) + lane;
                const float4* p1 = reinterpret_cast<const float4*>(
                    xTb + (size_t)s_mi[1 * 128 + px] * C1) + lane;
                const float4* p2 = reinterpret_cast<const float4*>(
                    xTb + (size_t)s_mi[2 * 128 + px] * C1) + lane;
                const float4* p3 = reinterpret_cast<const float4*>(
                    xTb + (size_t)s_mi[3 * 128 + px] * C1) + lane;
                float4 v0 = *p0, v1 = *p1, v2 = *p2, v3 = *p3;
                float ax = w0 * v0.x; ax = fmaf(w1, v1.x, ax);
                ax = fmaf(w2, v2.x, ax); ax = fmaf(w3, v3.x, ax);
                float ay = w0 * v0.y; ay = fmaf(w1, v1.y, ay);
                ay = fmaf(w2, v2.y, ay); ay = fmaf(w3, v3.y, ay);
                float az = w0 * v0.z; az = fmaf(w1, v1.z, az);
                az = fmaf(w2, v2.z, az); az = fmaf(w3, v3.z, az);
                float aw = w0 * v0.w; aw = fmaf(w1, v1.w, aw);
                aw = fmaf(w2, v2.w, aw); aw = fmaf(w3, v3.w, aw);
                uint32_t lo0, lo1;
                uint32_t hi0 = split_pack2(ax, ay, lo0);
                uint32_t hi1 = split_pack2(az, aw, lo1);
                *reinterpret_cast<uint2*>(Ah + px * LDA + lane * 4) = make_uint2(hi0, hi1);
                *reinterpret_cast<uint2*>(Al + px * LDA + lane * 4) = make_uint2(lo0, lo1);
            }
        }
        // ---- B: copy pre-split bf16 weights into smem (pure uint4 copy) ----
        {
            const int oc   = t >> 1;
            const int half = t & 1;
            const size_t src = ((size_t)tap * 128 + oc) * 128 + half * 64;
            const uint4* sH = reinterpret_cast<const uint4*>(g_wBh + src);
            const uint4* sL = reinterpret_cast<const uint4*>(g_wBl + src);
            uint4* dH = reinterpret_cast<uint4*>(Bh + oc * LDA + half * 64);
            uint4* dL = reinterpret_cast<uint4*>(Bl + oc * LDA + half * 64);
#pragma unroll
            for (int j = 0; j < 8; j++) { dH[j] = sH[j]; dL[j] = sL[j]; }
        }
        __syncthreads();

        // ---- MMA: 8 k-chunks x 3 terms x (4m x 2n) ----
        const int m0 = wm * 64;
        const int n0 = wn * 32;
#pragma unroll 1
        for (int kc = 0; kc < 8; kc++) {
            const int k0 = kc * 16;
            wmma::fragment<wmma::matrix_a, 16, 16, 16, __nv_bfloat16, wmma::row_major> ah[4], al[4];
            wmma::fragment<wmma::matrix_b, 16, 16, 16, __nv_bfloat16, wmma::col_major> bh[2], bl[2];
#pragma unroll
            for (int mt = 0; mt < 4; mt++) {
                wmma::load_matrix_sync(ah[mt], Ah + (m0 + mt * 16) * LDA + k0, LDA);
                wmma::load_matrix_sync(al[mt], Al + (m0 + mt * 16) * LDA + k0, LDA);
            }
#pragma unroll
            for (int nt = 0; nt < 2; nt++) {
                wmma::load_matrix_sync(bh[nt], Bh + (n0 + nt * 16) * LDA + k0, LDA);
                wmma::load_matrix_sync(bl[nt], Bl + (n0 + nt * 16) * LDA + k0, LDA);
            }
#pragma unroll
            for (int mt = 0; mt < 4; mt++) {
#pragma unroll
                for (int nt = 0; nt < 2; nt++) {
                    wmma::mma_sync(acc[mt][nt], ah[mt], bh[nt], acc[mt][nt]);
                    wmma::mma_sync(acc[mt][nt], ah[mt], bl[nt], acc[mt][nt]);
                    wmma::mma_sync(acc[mt][nt], al[mt], bh[nt], acc[mt][nt]);
                }
            }
        }
    }

    // ---- epilogue ----
    __syncthreads();
#pragma unroll
    for (int mt = 0; mt < 4; mt++)
#pragma unroll
        for (int nt = 0; nt < 2; nt++)
            wmma::store_matrix_sync(
                s_out + (wm * 64 + mt * 16) * LDO + wn * 32 + nt * 16,
                acc[mt][nt], LDO, wmma::mem_row_major);
    __syncthreads();

#pragma unroll 4
    for (int j = 0; j < 64; j++) {
        int i  = t + 256 * j;
        int oc = i >> 7;
        int px = i & 127;
        out[(size_t)(b * C2 + oc) * HW + pix0 + px] =
            s_out[px * LDO + oc] + s_bias[oc];
    }
}

// ============================================================================
extern "C" void kernel_launch(void* const* d_in, const int* in_sizes, int n_in,
                              void* d_out, int out_size) {
    const float* x    = (const float*)d_in[0];
    const float* ow   = (const float*)d_in[1];
    const float* ob   = (const float*)d_in[2];
    const float* wgt  = (const float*)d_in[3];
    const float* bias = (const float*)d_in[4];
    float* out = (float*)d_out;

    dim3 gn(Hh, BATCH);
    nhwc_kernel<<<gn, 256>>>(x);

    prep_w_kernel<<<(9 * 128 * 128 + 255) / 256, 256>>>(wgt);

    dim3 g1(Ww / OT, Hh / OT, BATCH);
    offset_conv_kernel<<<g1, 256>>>(x, ow, ob);

    cudaFuncSetAttribute(deform_wmma_kernel,
                         cudaFuncAttributeMaxDynamicSharedMemorySize,
                         SMEM_TOTAL_D);
    dim3 g2(HW / 128, BATCH);
    deform_wmma_kernel<<<g2, 256, SMEM_TOTAL_D>>>(bias, out);
}

// round 5
// speedup vs baseline: 1.3250x; 1.0166x over previous
#include <cuda_runtime.h>
#include <cuda_bf16.h>
#include <mma.h>
#include <cstdint>

using namespace nvcuda;

// ---------------------------------------------------------------------------
// DSConv2d: offset conv (3x3, 128->18) + deformable conv (3x3, 128->128)
// B=16, C1=C2=128, H=W=80, fp32.
// Deform conv: NHWC coalesced bilinear gather + WMMA bf16 3-term split GEMM.
// Round 5: 64px x 128oc blocks, 2 CTAs/SM for latency overlap.
// ---------------------------------------------------------------------------

#define Hh 80
#define Ww 80
#define HW 6400
#define C1 128
#define C2 128
#define BATCH 16
#define OFFC 18

static __device__ float g_offset[BATCH * OFFC * HW];           // 7.37 MB
static __device__ float g_xT[BATCH * HW * C1];                 // 52.4 MB NHWC
static __device__ __nv_bfloat16 g_wBh[9 * 128 * 128];          // wT hi [tap][oc][c]
static __device__ __nv_bfloat16 g_wBl[9 * 128 * 128];          // wT lo

// ============================================================================
// Kernel 0a: NCHW -> NHWC transform of x
// ============================================================================
__global__ __launch_bounds__(256) void nhwc_kernel(const float* __restrict__ x)
{
    __shared__ float tile[128][81];
    const int h = blockIdx.x;
    const int b = blockIdx.y;
    const int t = threadIdx.x;

    for (int idx = t; idx < 128 * 80; idx += 256) {
        int c = idx / 80;
        int w = idx - c * 80;
        tile[c][w] = x[((size_t)(b * C1 + c) * Hh + h) * Ww + w];
    }
    __syncthreads();
    for (int idx = t; idx < 80 * 128; idx += 256) {
        int w = idx >> 7;
        int c = idx & 127;
        g_xT[((size_t)b * HW + h * Ww + w) * C1 + c] = tile[c][w];
    }
}

// ============================================================================
// Kernel 0b: weight transpose + bf16 hi/lo pre-split
// ============================================================================
__global__ __launch_bounds__(256) void prep_w_kernel(const float* __restrict__ wgt)
{
    int i = blockIdx.x * 256 + threadIdx.x;
    if (i < 9 * 128 * 128) {
        int c    = i & 127;
        int rest = i >> 7;
        int oc   = rest & 127;
        int tap  = rest >> 7;
        float w = wgt[(oc * 128 + c) * 9 + tap];
        __nv_bfloat16 hi = __float2bfloat16_rn(w);
        __nv_bfloat16 lo = __float2bfloat16_rn(w - __bfloat162float(hi));
        g_wBh[i] = hi;
        g_wBl[i] = lo;
    }
}

// ============================================================================
// Kernel 1: offset conv (verified numerics, unchanged)
// ============================================================================
#define OT 16
#define OCC 16

__global__ __launch_bounds__(256) void offset_conv_kernel(
    const float* __restrict__ x,
    const float* __restrict__ ow,
    const float* __restrict__ ob)
{
    __shared__ float xs[OCC][18][18];
    __shared__ float ws[OCC * 9][20];

    const int b   = blockIdx.z;
    const int by0 = blockIdx.y * OT;
    const int bx0 = blockIdx.x * OT;
    const int t   = threadIdx.x;
    const int tx  = t & 15;
    const int ty  = t >> 4;

    float acc[18];
#pragma unroll
    for (int i = 0; i < 18; i++) acc[i] = 0.f;

    for (int cb = 0; cb < C1; cb += OCC) {
        __syncthreads();
        for (int i = t; i < OCC * 18 * 18; i += 256) {
            int c   = i / 324;
            int rem = i - c * 324;
            int r   = rem / 18;
            int col = rem - r * 18;
            int y   = by0 - 1 + r;
            int xx  = bx0 - 1 + col;
            float v = 0.f;
            if (y >= 0 && y < Hh && xx >= 0 && xx < Ww)
                v = x[(b * C1 + cb + c) * HW + y * Ww + xx];
            xs[c][r][col] = v;
        }
        for (int i = t; i < 18 * 36; i += 256) {
            int oc = i / 36;
            int q  = i - oc * 36;
            float4 v = *reinterpret_cast<const float4*>(ow + oc * (C1 * 9) + cb * 9 + q * 4);
            int k = q * 4;
            ws[k + 0][oc] = v.x;
            ws[k + 1][oc] = v.y;
            ws[k + 2][oc] = v.z;
            ws[k + 3][oc] = v.w;
        }
        __syncthreads();

#pragma unroll 1
        for (int c = 0; c < OCC; c++) {
#pragma unroll
            for (int tap = 0; tap < 9; tap++) {
                const int ki = tap / 3;
                const int kj = tap % 3;
                float xv = xs[c][ty + ki][tx + kj];
                const float* wp = &ws[c * 9 + tap][0];
                float wreg[18];
                float4 w0 = *reinterpret_cast<const float4*>(wp);
                float4 w1 = *reinterpret_cast<const float4*>(wp + 4);
                float4 w2 = *reinterpret_cast<const float4*>(wp + 8);
                float4 w3 = *reinterpret_cast<const float4*>(wp + 12);
                wreg[0] = w0.x;  wreg[1] = w0.y;  wreg[2] = w0.z;  wreg[3] = w0.w;
                wreg[4] = w1.x;  wreg[5] = w1.y;  wreg[6] = w1.z;  wreg[7] = w1.w;
                wreg[8] = w2.x;  wreg[9] = w2.y;  wreg[10] = w2.z; wreg[11] = w2.w;
                wreg[12] = w3.x; wreg[13] = w3.y; wreg[14] = w3.z; wreg[15] = w3.w;
                wreg[16] = wp[16]; wreg[17] = wp[17];
#pragma unroll
                for (int j = 0; j < 18; j++)
                    acc[j] = fmaf(xv, wreg[j], acc[j]);
            }
        }
    }

    const int pix = (by0 + ty) * Ww + bx0 + tx;
#pragma unroll
    for (int ch = 0; ch < 18; ch++)
        g_offset[(b * OFFC + ch) * HW + pix] = acc[ch] + ob[ch];
}

// ============================================================================
// Kernel 2: deformable conv. 64px x 128oc per block, 2 CTAs/SM.
// 8 warps = 2 m-groups (32px) x 4 n-groups (32oc); acc 2x2 frags/warp.
// ============================================================================
#define MPX 64
#define LDA 136
#define LDO 132

#define SMO_BIAS 0
#define SMO_MW   512
#define SMO_MI   1536
#define SMO_AH   2560
#define SMO_AL   (SMO_AH + MPX * LDA * 2)        // +17408
#define SMO_BH   (SMO_AL + MPX * LDA * 2)
#define SMO_BL   (SMO_BH + 128 * LDA * 2)
#define SMEM_TOTAL_D (SMO_BL + 128 * LDA * 2)    // 107008

__device__ __forceinline__ uint32_t split_pack2(float va, float vb,
                                                uint32_t& lo_pair) {
    __nv_bfloat16 ha = __float2bfloat16_rn(va);
    __nv_bfloat16 hb = __float2bfloat16_rn(vb);
    __nv_bfloat16 la = __float2bfloat16_rn(va - __bfloat162float(ha));
    __nv_bfloat16 lb = __float2bfloat16_rn(vb - __bfloat162float(hb));
    lo_pair = ((uint32_t)__bfloat16_as_ushort(lb) << 16) |
              (uint32_t)__bfloat16_as_ushort(la);
    return ((uint32_t)__bfloat16_as_ushort(hb) << 16) |
           (uint32_t)__bfloat16_as_ushort(ha);
}

__global__ __launch_bounds__(256, 2)
void deform_wmma_kernel(const float* __restrict__ bias,
                        float* __restrict__ out)
{
    extern __shared__ char smem[];
    float* s_bias = reinterpret_cast<float*>(smem + SMO_BIAS);
    float* s_mw   = reinterpret_cast<float*>(smem + SMO_MW);
    int*   s_mi   = reinterpret_cast<int*>(smem + SMO_MI);
    __nv_bfloat16* Ah = reinterpret_cast<__nv_bfloat16*>(smem + SMO_AH);
    __nv_bfloat16* Al = reinterpret_cast<__nv_bfloat16*>(smem + SMO_AL);
    __nv_bfloat16* Bh = reinterpret_cast<__nv_bfloat16*>(smem + SMO_BH);
    __nv_bfloat16* Bl = reinterpret_cast<__nv_bfloat16*>(smem + SMO_BL);
    float* s_out = reinterpret_cast<float*>(smem + SMO_AH);  // reuse post-MMA

    const int t    = threadIdx.x;
    const int wid  = t >> 5;
    const int lane = t & 31;
    const int b    = blockIdx.y;
    const int pix0 = blockIdx.x * MPX;
    const int wm   = wid & 1;    // 2 m-groups of 32 px
    const int wn   = wid >> 1;   // 4 n-groups of 32 oc

    const float* xTb = g_xT + (size_t)b * HW * C1;

    wmma::fragment<wmma::accumulator, 16, 16, 16, float> acc[2][2];
#pragma unroll
    for (int mt = 0; mt < 2; mt++)
#pragma unroll
        for (int nt = 0; nt < 2; nt++)
            wmma::fill_fragment(acc[mt][nt], 0.f);

    if (t < 128) s_bias[t] = bias[t];

#pragma unroll 1
    for (int tap = 0; tap < 9; tap++) {
        // ---- bilinear metadata for this tap's 64 px ----
        if (t < MPX) {
            const int pix = pix0 + t;
            const int ho  = pix / Ww;
            const int wo  = pix - ho * Ww;
            const int ki  = tap / 3;
            const int kj  = tap % 3;
            float dy = g_offset[(b * OFFC + 2 * tap) * HW + pix];
            float dx = g_offset[(b * OFFC + 2 * tap + 1) * HW + pix];
            float py  = (float)(ho - 1 + ki) + dy;
            float pxx = (float)(wo - 1 + kj) + dx;
            float y0 = floorf(py);
            float x0 = floorf(pxx);
            float wy1 = py - y0, wy0 = 1.f - wy1;
            float wx1 = pxx - x0, wx0 = 1.f - wx1;
#pragma unroll
            for (int cy = 0; cy < 2; cy++) {
#pragma unroll
                for (int cx = 0; cx < 2; cx++) {
                    float yc = y0 + (float)cy;
                    float xc = x0 + (float)cx;
                    bool valid = (yc >= 0.f) && (yc < (float)Hh) &&
                                 (xc >= 0.f) && (xc < (float)Ww);
                    int iy = (int)fminf(fmaxf(yc, 0.f), (float)(Hh - 1));
                    int ix = (int)fminf(fmaxf(xc, 0.f), (float)(Ww - 1));
                    int cr = cy * 2 + cx;
                    s_mw[cr * MPX + t] = valid ? ((cy ? wy1 : wy0) * (cx ? wx1 : wx0)) : 0.f;
                    s_mi[cr * MPX + t] = iy * Ww + ix;
                }
            }
        }
        __syncthreads();

        // ---- A: coalesced NHWC gather. warp -> 8 px, lane -> 4 channels ----
        {
            const int pxbase = wid * 8;
#pragma unroll 2
            for (int i = 0; i < 8; i++) {
                const int px = pxbase + i;
                const float w0 = s_mw[0 * MPX + px], w1 = s_mw[1 * MPX + px];
                const float w2 = s_mw[2 * MPX + px], w3 = s_mw[3 * MPX + px];
                const float4* p0 = reinterpret_cast<const float4*>(
                    xTb + (size_t)s_mi[0 * MPX + px] * C1) + lane;
                const float4* p1 = reinterpret_cast<const float4*>(
                    xTb + (size_t)s_mi[1 * MPX + px] * C1) + lane;
                const float4* p2 = reinterpret_cast<const float4*>(
                    xTb + (size_t)s_mi[2 * MPX + px] * C1) + lane;
                const float4* p3 = reinterpret_cast<const float4*>(
                    xTb + (size_t)s_mi[3 * MPX + px] * C1) + lane;
                float4 v0 = *p0, v1 = *p1, v2 = *p2, v3 = *p3;
                float ax = w0 * v0.x; ax = fmaf(w1, v1.x, ax);
                ax = fmaf(w2, v2.x, ax); ax = fmaf(w3, v3.x, ax);
                float ay = w0 * v0.y; ay = fmaf(w1, v1.y, ay);
                ay = fmaf(w2, v2.y, ay); ay = fmaf(w3, v3.y, ay);
                float az = w0 * v0.z; az = fmaf(w1, v1.z, az);
                az = fmaf(w2, v2.z, az); az = fmaf(w3, v3.z, az);
                float aw = w0 * v0.w; aw = fmaf(w1, v1.w, aw);
                aw = fmaf(w2, v2.w, aw); aw = fmaf(w3, v3.w, aw);
                uint32_t lo0, lo1;
                uint32_t hi0 = split_pack2(ax, ay, lo0);
                uint32_t hi1 = split_pack2(az, aw, lo1);
                *reinterpret_cast<uint2*>(Ah + px * LDA + lane * 4) = make_uint2(hi0, hi1);
                *reinterpret_cast<uint2*>(Al + px * LDA + lane * 4) = make_uint2(lo0, lo1);
            }
        }
        // ---- B: copy pre-split bf16 weights into smem ----
        {
            const int oc   = t >> 1;
            const int half = t & 1;
            const size_t src = ((size_t)tap * 128 + oc) * 128 + half * 64;
            const uint4* sH = reinterpret_cast<const uint4*>(g_wBh + src);
            const uint4* sL = reinterpret_cast<const uint4*>(g_wBl + src);
            uint4* dH = reinterpret_cast<uint4*>(Bh + oc * LDA + half * 64);
            uint4* dL = reinterpret_cast<uint4*>(Bl + oc * LDA + half * 64);
#pragma unroll
            for (int j = 0; j < 8; j++) { dH[j] = sH[j]; dL[j] = sL[j]; }
        }
        __syncthreads();

        // ---- MMA: 8 k-chunks x 3 terms x (2m x 2n) ----
        const int m0 = wm * 32;
        const int n0 = wn * 32;
#pragma unroll 1
        for (int kc = 0; kc < 8; kc++) {
            const int k0 = kc * 16;
            wmma::fragment<wmma::matrix_a, 16, 16, 16, __nv_bfloat16, wmma::row_major> ah[2], al[2];
            wmma::fragment<wmma::matrix_b, 16, 16, 16, __nv_bfloat16, wmma::col_major> bh[2], bl[2];
#pragma unroll
            for (int mt = 0; mt < 2; mt++) {
                wmma::load_matrix_sync(ah[mt], Ah + (m0 + mt * 16) * LDA + k0, LDA);
                wmma::load_matrix_sync(al[mt], Al + (m0 + mt * 16) * LDA + k0, LDA);
            }
#pragma unroll
            for (int nt = 0; nt < 2; nt++) {
                wmma::load_matrix_sync(bh[nt], Bh + (n0 + nt * 16) * LDA + k0, LDA);
                wmma::load_matrix_sync(bl[nt], Bl + (n0 + nt * 16) * LDA + k0, LDA);
            }
#pragma unroll
            for (int mt = 0; mt < 2; mt++) {
#pragma unroll
                for (int nt = 0; nt < 2; nt++) {
                    wmma::mma_sync(acc[mt][nt], ah[mt], bh[nt], acc[mt][nt]);
                    wmma::mma_sync(acc[mt][nt], ah[mt], bl[nt], acc[mt][nt]);
                    wmma::mma_sync(acc[mt][nt], al[mt], bh[nt], acc[mt][nt]);
                }
            }
        }
    }

    // ---- epilogue ----
    __syncthreads();
#pragma unroll
    for (int mt = 0; mt < 2; mt++)
#pragma unroll
        for (int nt = 0; nt < 2; nt++)
            wmma::store_matrix_sync(
                s_out + (wm * 32 + mt * 16) * LDO + wn * 32 + nt * 16,
                acc[mt][nt], LDO, wmma::mem_row_major);
    __syncthreads();

#pragma unroll 4
    for (int j = 0; j < 32; j++) {
        int i  = t + 256 * j;   // 8192 outputs
        int oc = i >> 6;
        int px = i & 63;
        out[(size_t)(b * C2 + oc) * HW + pix0 + px] =
            s_out[px * LDO + oc] + s_bias[oc];
    }
}

// ============================================================================
extern "C" void kernel_launch(void* const* d_in, const int* in_sizes, int n_in,
                              void* d_out, int out_size) {
    const float* x    = (const float*)d_in[0];
    const float* ow   = (const float*)d_in[1];
    const float* ob   = (const float*)d_in[2];
    const float* wgt  = (const float*)d_in[3];
    const float* bias = (const float*)d_in[4];
    float* out = (float*)d_out;

    dim3 gn(Hh, BATCH);
    nhwc_kernel<<<gn, 256>>>(x);

    prep_w_kernel<<<(9 * 128 * 128 + 255) / 256, 256>>>(wgt);

    dim3 g1(Ww / OT, Hh / OT, BATCH);
    offset_conv_kernel<<<g1, 256>>>(x, ow, ob);

    cudaFuncSetAttribute(deform_wmma_kernel,
                         cudaFuncAttributeMaxDynamicSharedMemorySize,
                         SMEM_TOTAL_D);
    dim3 g2(HW / MPX, BATCH);
    deform_wmma_kernel<<<g2, 256, SMEM_TOTAL_D>>>(bias, out);
}

// round 6
// speedup vs baseline: 1.9787x; 1.4933x over previous
#include <cuda_runtime.h>
#include <cuda_bf16.h>
#include <cstdint>

// ---------------------------------------------------------------------------
// DSConv2d: offset conv (3x3, 128->18) + deformable conv (3x3, 128->128)
// B=16, C1=C2=128, H=W=80, fp32.
// Deform conv: NHWC gather + raw mma.m16n8k16 bf16 3-term split GEMM.
// Round 6: B weights pre-packed in mma fragment layout (no B smem round-trip).
// ---------------------------------------------------------------------------

#define Hh 80
#define Ww 80
#define HW 6400
#define C1 128
#define C2 128
#define BATCH 16
#define OFFC 18

static __device__ float g_offset[BATCH * OFFC * HW];   // 7.37 MB
static __device__ float g_xT[BATCH * HW * C1];         // 52.4 MB NHWC
static __device__ uint4 g_wF[9 * 8 * 16 * 32];         // frag-packed weights (hi,hi,lo,lo)

// ============================================================================
// Kernel 0a: NCHW -> NHWC transform of x
// ============================================================================
__global__ __launch_bounds__(256) void nhwc_kernel(const float* __restrict__ x)
{
    __shared__ float tile[128][81];
    const int h = blockIdx.x;
    const int b = blockIdx.y;
    const int t = threadIdx.x;

    for (int idx = t; idx < 128 * 80; idx += 256) {
        int c = idx / 80;
        int w = idx - c * 80;
        tile[c][w] = x[((size_t)(b * C1 + c) * Hh + h) * Ww + w];
    }
    __syncthreads();
    for (int idx = t; idx < 80 * 128; idx += 256) {
        int w = idx >> 7;
        int c = idx & 127;
        g_xT[((size_t)b * HW + h * Ww + w) * C1 + c] = tile[c][w];
    }
}

// ============================================================================
// Kernel 0b: weight -> mma.m16n8k16 B-fragment packing with bf16 hi/lo split.
// B matrix for tap: B[k=c][n=oc] = wgt[oc][c][tap].
// Fragment (kc, nf): lane holds {b[kb][n], b[kb+1][n]} and {b[kb+8][n], b[kb+9][n]}
// with n = nf*8 + lane/4, kb = kc*16 + (lane%4)*2.  Packed uint4 = {h0,h1,l0,l1}.
// ============================================================================
__global__ __launch_bounds__(256) void prep_wfrag_kernel(const float* __restrict__ wgt)
{
    int i = blockIdx.x * 256 + threadIdx.x;
    if (i >= 9 * 8 * 16 * 32) return;
    int lane = i & 31;
    int nf   = (i >> 5) & 15;
    int kc   = (i >> 9) & 7;
    int tap  = i >> 12;
    int n  = nf * 8 + (lane >> 2);
    int kb = kc * 16 + (lane & 3) * 2;

    float w00 = wgt[(n * 128 + kb + 0) * 9 + tap];
    float w01 = wgt[(n * 128 + kb + 1) * 9 + tap];
    float w10 = wgt[(n * 128 + kb + 8) * 9 + tap];
    float w11 = wgt[(n * 128 + kb + 9) * 9 + tap];

    __nv_bfloat16 h00 = __float2bfloat16_rn(w00);
    __nv_bfloat16 h01 = __float2bfloat16_rn(w01);
    __nv_bfloat16 h10 = __float2bfloat16_rn(w10);
    __nv_bfloat16 h11 = __float2bfloat16_rn(w11);
    __nv_bfloat16 l00 = __float2bfloat16_rn(w00 - __bfloat162float(h00));
    __nv_bfloat16 l01 = __float2bfloat16_rn(w01 - __bfloat162float(h01));
    __nv_bfloat16 l10 = __float2bfloat16_rn(w10 - __bfloat162float(h10));
    __nv_bfloat16 l11 = __float2bfloat16_rn(w11 - __bfloat162float(h11));

    uint4 v;
    v.x = ((uint32_t)__bfloat16_as_ushort(h01) << 16) | (uint32_t)__bfloat16_as_ushort(h00);
    v.y = ((uint32_t)__bfloat16_as_ushort(h11) << 16) | (uint32_t)__bfloat16_as_ushort(h10);
    v.z = ((uint32_t)__bfloat16_as_ushort(l01) << 16) | (uint32_t)__bfloat16_as_ushort(l00);
    v.w = ((uint32_t)__bfloat16_as_ushort(l11) << 16) | (uint32_t)__bfloat16_as_ushort(l10);
    g_wF[i] = v;
}

// ============================================================================
// Kernel 1: offset conv (verified numerics, unchanged)
// ============================================================================
#define OT 16
#define OCC 16

__global__ __launch_bounds__(256) void offset_conv_kernel(
    const float* __restrict__ x,
    const float* __restrict__ ow,
    const float* __restrict__ ob)
{
    __shared__ float xs[OCC][18][18];
    __shared__ float ws[OCC * 9][20];

    const int b   = blockIdx.z;
    const int by0 = blockIdx.y * OT;
    const int bx0 = blockIdx.x * OT;
    const int t   = threadIdx.x;
    const int tx  = t & 15;
    const int ty  = t >> 4;

    float acc[18];
#pragma unroll
    for (int i = 0; i < 18; i++) acc[i] = 0.f;

    for (int cb = 0; cb < C1; cb += OCC) {
        __syncthreads();
        for (int i = t; i < OCC * 18 * 18; i += 256) {
            int c   = i / 324;
            int rem = i - c * 324;
            int r   = rem / 18;
            int col = rem - r * 18;
            int y   = by0 - 1 + r;
            int xx  = bx0 - 1 + col;
            float v = 0.f;
            if (y >= 0 && y < Hh && xx >= 0 && xx < Ww)
                v = x[(b * C1 + cb + c) * HW + y * Ww + xx];
            xs[c][r][col] = v;
        }
        for (int i = t; i < 18 * 36; i += 256) {
            int oc = i / 36;
            int q  = i - oc * 36;
            float4 v = *reinterpret_cast<const float4*>(ow + oc * (C1 * 9) + cb * 9 + q * 4);
            int k = q * 4;
            ws[k + 0][oc] = v.x;
            ws[k + 1][oc] = v.y;
            ws[k + 2][oc] = v.z;
            ws[k + 3][oc] = v.w;
        }
        __syncthreads();

#pragma unroll 1
        for (int c = 0; c < OCC; c++) {
#pragma unroll
            for (int tap = 0; tap < 9; tap++) {
                const int ki = tap / 3;
                const int kj = tap % 3;
                float xv = xs[c][ty + ki][tx + kj];
                const float* wp = &ws[c * 9 + tap][0];
                float wreg[18];
                float4 w0 = *reinterpret_cast<const float4*>(wp);
                float4 w1 = *reinterpret_cast<const float4*>(wp + 4);
                float4 w2 = *reinterpret_cast<const float4*>(wp + 8);
                float4 w3 = *reinterpret_cast<const float4*>(wp + 12);
                wreg[0] = w0.x;  wreg[1] = w0.y;  wreg[2] = w0.z;  wreg[3] = w0.w;
                wreg[4] = w1.x;  wreg[5] = w1.y;  wreg[6] = w1.z;  wreg[7] = w1.w;
                wreg[8] = w2.x;  wreg[9] = w2.y;  wreg[10] = w2.z; wreg[11] = w2.w;
                wreg[12] = w3.x; wreg[13] = w3.y; wreg[14] = w3.z; wreg[15] = w3.w;
                wreg[16] = wp[16]; wreg[17] = wp[17];
#pragma unroll
                for (int j = 0; j < 18; j++)
                    acc[j] = fmaf(xv, wreg[j], acc[j]);
            }
        }
    }

    const int pix = (by0 + ty) * Ww + bx0 + tx;
#pragma unroll
    for (int ch = 0; ch < 18; ch++)
        g_offset[(b * OFFC + ch) * HW + pix] = acc[ch] + ob[ch];
}

// ============================================================================
// Kernel 2: deformable conv. 64px x 128oc per block, 2 CTAs/SM.
// 8 warps = 2 m-groups (32px) x 4 n-groups (32oc).
// A: NHWC gather -> bf16 hi/lo split -> smem -> ldmatrix.
// B: direct LDG.128 of fragment-packed weights (no smem).
// MMA: raw mma.sync.m16n8k16 bf16, 3-term split.
// ============================================================================
#define MPX 64
#define LDA 136
#define LDO 132

#define SMO_BIAS 0
#define SMO_MW   512
#define SMO_MI   1536
#define SMO_AH   2560
#define SMO_AL   (SMO_AH + MPX * LDA * 2)        // +17408
#define SMEM_TOTAL_D (SMO_AL + MPX * LDA * 2)    // 37376

__device__ __forceinline__ uint32_t smem_u32(const void* p) {
    uint32_t a;
    asm("{ .reg .u64 t; cvta.to.shared.u64 t, %1; cvt.u32.u64 %0, t; }"
        : "=r"(a) : "l"(p));
    return a;
}

__device__ __forceinline__ void ldsm_x4(uint32_t* r, uint32_t saddr) {
    asm volatile("ldmatrix.sync.aligned.m8n8.x4.shared.b16 {%0,%1,%2,%3}, [%4];"
                 : "=r"(r[0]), "=r"(r[1]), "=r"(r[2]), "=r"(r[3])
                 : "r"(saddr));
}

__device__ __forceinline__ void mma16816(float* d, const uint32_t* a,
                                         const uint32_t* b) {
    asm volatile(
        "mma.sync.aligned.m16n8k16.row.col.f32.bf16.bf16.f32 "
        "{%0,%1,%2,%3}, {%4,%5,%6,%7}, {%8,%9}, {%0,%1,%2,%3};"
        : "+f"(d[0]), "+f"(d[1]), "+f"(d[2]), "+f"(d[3])
        : "r"(a[0]), "r"(a[1]), "r"(a[2]), "r"(a[3]),
          "r"(b[0]), "r"(b[1]));
}

__device__ __forceinline__ uint32_t split_pack2(float va, float vb,
                                                uint32_t& lo_pair) {
    __nv_bfloat16 ha = __float2bfloat16_rn(va);
    __nv_bfloat16 hb = __float2bfloat16_rn(vb);
    __nv_bfloat16 la = __float2bfloat16_rn(va - __bfloat162float(ha));
    __nv_bfloat16 lb = __float2bfloat16_rn(vb - __bfloat162float(hb));
    lo_pair = ((uint32_t)__bfloat16_as_ushort(lb) << 16) |
              (uint32_t)__bfloat16_as_ushort(la);
    return ((uint32_t)__bfloat16_as_ushort(hb) << 16) |
           (uint32_t)__bfloat16_as_ushort(ha);
}

__global__ __launch_bounds__(256, 2)
void deform_mma_kernel(const float* __restrict__ bias,
                       float* __restrict__ out)
{
    extern __shared__ char smem[];
    const uint32_t sb = smem_u32(smem);
    float* s_bias = reinterpret_cast<float*>(smem + SMO_BIAS);
    float* s_mw   = reinterpret_cast<float*>(smem + SMO_MW);
    int*   s_mi   = reinterpret_cast<int*>(smem + SMO_MI);
    float* s_out  = reinterpret_cast<float*>(smem + SMO_AH);  // reuse post-MMA

    const int t    = threadIdx.x;
    const int wid  = t >> 5;
    const int lane = t & 31;
    const int b    = blockIdx.y;
    const int pix0 = blockIdx.x * MPX;
    const int wm   = wid & 1;    // m-group: 32 px
    const int wn   = wid >> 1;   // n-group: 32 oc

    const float* xTb = g_xT + (size_t)b * HW * C1;

    float acc[2][4][4];
#pragma unroll
    for (int mt = 0; mt < 2; mt++)
#pragma unroll
        for (int j = 0; j < 4; j++)
#pragma unroll
            for (int r = 0; r < 4; r++) acc[mt][j][r] = 0.f;

    if (t < 128) s_bias[t] = bias[t];

    // ldmatrix lane addressing (constant across taps)
    const int tile = lane >> 3;
    const int rr   = ((tile & 1) << 3) + (lane & 7);
    const int cb   = (tile >> 1) << 3;

#pragma unroll 1
    for (int tap = 0; tap < 9; tap++) {
        // ---- bilinear metadata for this tap's 64 px ----
        if (t < MPX) {
            const int pix = pix0 + t;
            const int ho  = pix / Ww;
            const int wo  = pix - ho * Ww;
            const int ki  = tap / 3;
            const int kj  = tap % 3;
            float dy = g_offset[(b * OFFC + 2 * tap) * HW + pix];
            float dx = g_offset[(b * OFFC + 2 * tap + 1) * HW + pix];
            float py  = (float)(ho - 1 + ki) + dy;
            float pxx = (float)(wo - 1 + kj) + dx;
            float y0 = floorf(py);
            float x0 = floorf(pxx);
            float wy1 = py - y0, wy0 = 1.f - wy1;
            float wx1 = pxx - x0, wx0 = 1.f - wx1;
#pragma unroll
            for (int cy = 0; cy < 2; cy++) {
#pragma unroll
                for (int cx = 0; cx < 2; cx++) {
                    float yc = y0 + (float)cy;
                    float xc = x0 + (float)cx;
                    bool valid = (yc >= 0.f) && (yc < (float)Hh) &&
                                 (xc >= 0.f) && (xc < (float)Ww);
                    int iy = (int)fminf(fmaxf(yc, 0.f), (float)(Hh - 1));
                    int ix = (int)fminf(fmaxf(xc, 0.f), (float)(Ww - 1));
                    int cr = cy * 2 + cx;
                    s_mw[cr * MPX + t] = valid ? ((cy ? wy1 : wy0) * (cx ? wx1 : wx0)) : 0.f;
                    s_mi[cr * MPX + t] = iy * Ww + ix;
                }
            }
        }
        __syncthreads();   // also guards A-tile reuse from previous tap's MMA

        // ---- A: coalesced NHWC gather, split, store to smem ----
        {
            __nv_bfloat16* Ah = reinterpret_cast<__nv_bfloat16*>(smem + SMO_AH);
            __nv_bfloat16* Al = reinterpret_cast<__nv_bfloat16*>(smem + SMO_AL);
            const int pxbase = wid * 8;
#pragma unroll 2
            for (int i = 0; i < 8; i++) {
                const int px = pxbase + i;
                const float w0 = s_mw[0 * MPX + px], w1 = s_mw[1 * MPX + px];
                const float w2 = s_mw[2 * MPX + px], w3 = s_mw[3 * MPX + px];
                const float4* p0 = reinterpret_cast<const float4*>(
                    xTb + (size_t)s_mi[0 * MPX + px] * C1) + lane;
                const float4* p1 = reinterpret_cast<const float4*>(
                    xTb + (size_t)s_mi[1 * MPX + px] * C1) + lane;
                const float4* p2 = reinterpret_cast<const float4*>(
                    xTb + (size_t)s_mi[2 * MPX + px] * C1) + lane;
                const float4* p3 = reinterpret_cast<const float4*>(
                    xTb + (size_t)s_mi[3 * MPX + px] * C1) + lane;
                float4 v0 = *p0, v1 = *p1, v2 = *p2, v3 = *p3;
                float ax = w0 * v0.x; ax = fmaf(w1, v1.x, ax);
                ax = fmaf(w2, v2.x, ax); ax = fmaf(w3, v3.x, ax);
                float ay = w0 * v0.y; ay = fmaf(w1, v1.y, ay);
                ay = fmaf(w2, v2.y, ay); ay = fmaf(w3, v3.y, ay);
                float az = w0 * v0.z; az = fmaf(w1, v1.z, az);
                az = fmaf(w2, v2.z, az); az = fmaf(w3, v3.z, az);
                float aw = w0 * v0.w; aw = fmaf(w1, v1.w, aw);
                aw = fmaf(w2, v2.w, aw); aw = fmaf(w3, v3.w, aw);
                uint32_t lo0, lo1;
                uint32_t hi0 = split_pack2(ax, ay, lo0);
                uint32_t hi1 = split_pack2(az, aw, lo1);
                *reinterpret_cast<uint2*>(Ah + px * LDA + lane * 4) = make_uint2(hi0, hi1);
                *reinterpret_cast<uint2*>(Al + px * LDA + lane * 4) = make_uint2(lo0, lo1);
            }
        }
        __syncthreads();

        // ---- MMA: 8 k-chunks; A via ldmatrix, B via frag-packed LDG ----
        const int m0 = wm * 32;
#pragma unroll 1
        for (int kc = 0; kc < 8; kc++) {
            uint32_t bh[4][2], bl[4][2];
            const uint4* wf = g_wF + (((size_t)tap * 8 + kc) * 16 + wn * 4) * 32 + lane;
#pragma unroll
            for (int j = 0; j < 4; j++) {
                uint4 bv = wf[j * 32];
                bh[j][0] = bv.x; bh[j][1] = bv.y;
                bl[j][0] = bv.z; bl[j][1] = bv.w;
            }
            uint32_t ah[2][4], al[2][4];
#pragma unroll
            for (int mt = 0; mt < 2; mt++) {
                uint32_t off = ((m0 + mt * 16 + rr) * LDA + kc * 16 + cb) * 2;
                ldsm_x4(ah[mt], sb + SMO_AH + off);
                ldsm_x4(al[mt], sb + SMO_AL + off);
            }
#pragma unroll
            for (int mt = 0; mt < 2; mt++) {
#pragma unroll
                for (int j = 0; j < 4; j++) {
                    mma16816(acc[mt][j], ah[mt], bh[j]);
                    mma16816(acc[mt][j], ah[mt], bl[j]);
                    mma16816(acc[mt][j], al[mt], bh[j]);
                }
            }
        }
    }

    // ---- epilogue: D frags -> smem [px][oc] -> coalesced gmem ----
    __syncthreads();
    {
        const int r0 = lane >> 2;
        const int c0 = (lane & 3) * 2;
#pragma unroll
        for (int mt = 0; mt < 2; mt++) {
#pragma unroll
            for (int j = 0; j < 4; j++) {
                const int row = wm * 32 + mt * 16 + r0;
                const int col = wn * 32 + j * 8 + c0;
                *reinterpret_cast<float2*>(s_out + row * LDO + col) =
                    make_float2(acc[mt][j][0], acc[mt][j][1]);
                *reinterpret_cast<float2*>(s_out + (row + 8) * LDO + col) =
                    make_float2(acc[mt][j][2], acc[mt][j][3]);
            }
        }
    }
    __syncthreads();

#pragma unroll 4
    for (int j = 0; j < 32; j++) {
        int i  = t + 256 * j;   // 8192 outputs
        int oc = i >> 6;
        int px = i & 63;
        out[(size_t)(b * C2 + oc) * HW + pix0 + px] =
            s_out[px * LDO + oc] + s_bias[oc];
    }
}

// ============================================================================
extern "C" void kernel_launch(void* const* d_in, const int* in_sizes, int n_in,
                              void* d_out, int out_size) {
    const float* x    = (const float*)d_in[0];
    const float* ow   = (const float*)d_in[1];
    const float* ob   = (const float*)d_in[2];
    const float* wgt  = (const float*)d_in[3];
    const float* bias = (const float*)d_in[4];
    float* out = (float*)d_out;

    dim3 gn(Hh, BATCH);
    nhwc_kernel<<<gn, 256>>>(x);

    prep_wfrag_kernel<<<(9 * 8 * 16 * 32 + 255) / 256, 256>>>(wgt);

    dim3 g1(Ww / OT, Hh / OT, BATCH);
    offset_conv_kernel<<<g1, 256>>>(x, ow, ob);

    cudaFuncSetAttribute(deform_mma_kernel,
                         cudaFuncAttributeMaxDynamicSharedMemorySize,
                         SMEM_TOTAL_D);
    dim3 g2(HW / MPX, BATCH);
    deform_mma_kernel<<<g2, 256, SMEM_TOTAL_D>>>(bias, out);
}

// round 7
// speedup vs baseline: 2.1014x; 1.0620x over previous
#include <cuda_runtime.h>
#include <cuda_bf16.h>
#include <cstdint>

// ---------------------------------------------------------------------------
// DSConv2d: offset conv (3x3, 128->18) + deformable conv (3x3, 128->128)
// B=16, C1=C2=128, H=W=80, fp32.
// Deform conv: NHWC gather + raw mma.m16n8k16 bf16 3-term split GEMM.
// Round 7: software pipeline — double-buffered A, register meta, 1 sync/tap.
// ---------------------------------------------------------------------------

#define Hh 80
#define Ww 80
#define HW 6400
#define C1 128
#define C2 128
#define BATCH 16
#define OFFC 18

static __device__ float g_offset[BATCH * OFFC * HW];   // 7.37 MB
static __device__ float g_xT[BATCH * HW * C1];         // 52.4 MB NHWC
static __device__ uint4 g_wF[9 * 8 * 16 * 32];         // frag-packed weights (h,h,l,l)

// ============================================================================
// Kernel 0a: NCHW -> NHWC transform of x
// ============================================================================
__global__ __launch_bounds__(256) void nhwc_kernel(const float* __restrict__ x)
{
    __shared__ float tile[128][81];
    const int h = blockIdx.x;
    const int b = blockIdx.y;
    const int t = threadIdx.x;

    for (int idx = t; idx < 128 * 80; idx += 256) {
        int c = idx / 80;
        int w = idx - c * 80;
        tile[c][w] = x[((size_t)(b * C1 + c) * Hh + h) * Ww + w];
    }
    __syncthreads();
    for (int idx = t; idx < 80 * 128; idx += 256) {
        int w = idx >> 7;
        int c = idx & 127;
        g_xT[((size_t)b * HW + h * Ww + w) * C1 + c] = tile[c][w];
    }
}

// ============================================================================
// Kernel 0b: weight -> mma.m16n8k16 B-fragment packing with bf16 hi/lo split.
// ============================================================================
__global__ __launch_bounds__(256) void prep_wfrag_kernel(const float* __restrict__ wgt)
{
    int i = blockIdx.x * 256 + threadIdx.x;
    if (i >= 9 * 8 * 16 * 32) return;
    int lane = i & 31;
    int nf   = (i >> 5) & 15;
    int kc   = (i >> 9) & 7;
    int tap  = i >> 12;
    int n  = nf * 8 + (lane >> 2);
    int kb = kc * 16 + (lane & 3) * 2;

    float w00 = wgt[(n * 128 + kb + 0) * 9 + tap];
    float w01 = wgt[(n * 128 + kb + 1) * 9 + tap];
    float w10 = wgt[(n * 128 + kb + 8) * 9 + tap];
    float w11 = wgt[(n * 128 + kb + 9) * 9 + tap];

    __nv_bfloat16 h00 = __float2bfloat16_rn(w00);
    __nv_bfloat16 h01 = __float2bfloat16_rn(w01);
    __nv_bfloat16 h10 = __float2bfloat16_rn(w10);
    __nv_bfloat16 h11 = __float2bfloat16_rn(w11);
    __nv_bfloat16 l00 = __float2bfloat16_rn(w00 - __bfloat162float(h00));
    __nv_bfloat16 l01 = __float2bfloat16_rn(w01 - __bfloat162float(h01));
    __nv_bfloat16 l10 = __float2bfloat16_rn(w10 - __bfloat162float(h10));
    __nv_bfloat16 l11 = __float2bfloat16_rn(w11 - __bfloat162float(h11));

    uint4 v;
    v.x = ((uint32_t)__bfloat16_as_ushort(h01) << 16) | (uint32_t)__bfloat16_as_ushort(h00);
    v.y = ((uint32_t)__bfloat16_as_ushort(h11) << 16) | (uint32_t)__bfloat16_as_ushort(h10);
    v.z = ((uint32_t)__bfloat16_as_ushort(l01) << 16) | (uint32_t)__bfloat16_as_ushort(l00);
    v.w = ((uint32_t)__bfloat16_as_ushort(l11) << 16) | (uint32_t)__bfloat16_as_ushort(l10);
    g_wF[i] = v;
}

// ============================================================================
// Kernel 1: offset conv (verified numerics, unchanged — near fp32 SIMT floor)
// ============================================================================
#define OT 16
#define OCC 16

__global__ __launch_bounds__(256) void offset_conv_kernel(
    const float* __restrict__ x,
    const float* __restrict__ ow,
    const float* __restrict__ ob)
{
    __shared__ float xs[OCC][18][18];
    __shared__ float ws[OCC * 9][20];

    const int b   = blockIdx.z;
    const int by0 = blockIdx.y * OT;
    const int bx0 = blockIdx.x * OT;
    const int t   = threadIdx.x;
    const int tx  = t & 15;
    const int ty  = t >> 4;

    float acc[18];
#pragma unroll
    for (int i = 0; i < 18; i++) acc[i] = 0.f;

    for (int cb = 0; cb < C1; cb += OCC) {
        __syncthreads();
        for (int i = t; i < OCC * 18 * 18; i += 256) {
            int c   = i / 324;
            int rem = i - c * 324;
            int r   = rem / 18;
            int col = rem - r * 18;
            int y   = by0 - 1 + r;
            int xx  = bx0 - 1 + col;
            float v = 0.f;
            if (y >= 0 && y < Hh && xx >= 0 && xx < Ww)
                v = x[(b * C1 + cb + c) * HW + y * Ww + xx];
            xs[c][r][col] = v;
        }
        for (int i = t; i < 18 * 36; i += 256) {
            int oc = i / 36;
            int q  = i - oc * 36;
            float4 v = *reinterpret_cast<const float4*>(ow + oc * (C1 * 9) + cb * 9 + q * 4);
            int k = q * 4;
            ws[k + 0][oc] = v.x;
            ws[k + 1][oc] = v.y;
            ws[k + 2][oc] = v.z;
            ws[k + 3][oc] = v.w;
        }
        __syncthreads();

#pragma unroll 1
        for (int c = 0; c < OCC; c++) {
#pragma unroll
            for (int tap = 0; tap < 9; tap++) {
                const int ki = tap / 3;
                const int kj = tap % 3;
                float xv = xs[c][ty + ki][tx + kj];
                const float* wp = &ws[c * 9 + tap][0];
                float wreg[18];
                float4 w0 = *reinterpret_cast<const float4*>(wp);
                float4 w1 = *reinterpret_cast<const float4*>(wp + 4);
                float4 w2 = *reinterpret_cast<const float4*>(wp + 8);
                float4 w3 = *reinterpret_cast<const float4*>(wp + 12);
                wreg[0] = w0.x;  wreg[1] = w0.y;  wreg[2] = w0.z;  wreg[3] = w0.w;
                wreg[4] = w1.x;  wreg[5] = w1.y;  wreg[6] = w1.z;  wreg[7] = w1.w;
                wreg[8] = w2.x;  wreg[9] = w2.y;  wreg[10] = w2.z; wreg[11] = w2.w;
                wreg[12] = w3.x; wreg[13] = w3.y; wreg[14] = w3.z; wreg[15] = w3.w;
                wreg[16] = wp[16]; wreg[17] = wp[17];
#pragma unroll
                for (int j = 0; j < 18; j++)
                    acc[j] = fmaf(xv, wreg[j], acc[j]);
            }
        }
    }

    const int pix = (by0 + ty) * Ww + bx0 + tx;
#pragma unroll
    for (int ch = 0; ch < 18; ch++)
        g_offset[(b * OFFC + ch) * HW + pix] = acc[ch] + ob[ch];
}

// ============================================================================
// Kernel 2: deformable conv. 64px x 128oc, 2 CTAs/SM, software-pipelined.
// A double-buffered in smem; bilinear meta in registers (shfl broadcast);
// B via fragment-packed LDG; one __syncthreads per tap.
// ============================================================================
#define MPX 64
#define LDA 136
#define LDO 132

#define SMO_BIAS 0
#define SMO_BUF0 1024
#define ABYTES   (MPX * LDA * 2)          // 17408 per matrix
#define BUFSZ    (2 * ABYTES)             // Ah + Al = 34816
#define SMO_BUF1 (SMO_BUF0 + BUFSZ)       // 35840
#define SMEM_TOTAL_D (SMO_BUF1 + BUFSZ)   // 70656

__device__ __forceinline__ uint32_t smem_u32(const void* p) {
    uint32_t a;
    asm("{ .reg .u64 t; cvta.to.shared.u64 t, %1; cvt.u32.u64 %0, t; }"
        : "=r"(a) : "l"(p));
    return a;
}

__device__ __forceinline__ void ldsm_x4(uint32_t* r, uint32_t saddr) {
    asm volatile("ldmatrix.sync.aligned.m8n8.x4.shared.b16 {%0,%1,%2,%3}, [%4];"
                 : "=r"(r[0]), "=r"(r[1]), "=r"(r[2]), "=r"(r[3])
                 : "r"(saddr));
}

__device__ __forceinline__ void mma16816(float* d, const uint32_t* a,
                                         const uint32_t* b) {
    asm volatile(
        "mma.sync.aligned.m16n8k16.row.col.f32.bf16.bf16.f32 "
        "{%0,%1,%2,%3}, {%4,%5,%6,%7}, {%8,%9}, {%0,%1,%2,%3};"
        : "+f"(d[0]), "+f"(d[1]), "+f"(d[2]), "+f"(d[3])
        : "r"(a[0]), "r"(a[1]), "r"(a[2]), "r"(a[3]),
          "r"(b[0]), "r"(b[1]));
}

__device__ __forceinline__ uint32_t split_pack2(float va, float vb,
                                                uint32_t& lo_pair) {
    __nv_bfloat16 ha = __float2bfloat16_rn(va);
    __nv_bfloat16 hb = __float2bfloat16_rn(vb);
    __nv_bfloat16 la = __float2bfloat16_rn(va - __bfloat162float(ha));
    __nv_bfloat16 lb = __float2bfloat16_rn(vb - __bfloat162float(hb));
    lo_pair = ((uint32_t)__bfloat16_as_ushort(lb) << 16) |
              (uint32_t)__bfloat16_as_ushort(la);
    return ((uint32_t)__bfloat16_as_ushort(hb) << 16) |
           (uint32_t)__bfloat16_as_ushort(ha);
}

__global__ __launch_bounds__(256, 2)
void deform_mma_kernel(const float* __restrict__ bias,
                       float* __restrict__ out)
{
    extern __shared__ char smem[];
    const uint32_t sb = smem_u32(smem);
    float* s_bias = reinterpret_cast<float*>(smem + SMO_BIAS);
    float* s_out  = reinterpret_cast<float*>(smem + SMO_BUF0);  // reuse post-MMA

    const int t    = threadIdx.x;
    const int wid  = t >> 5;
    const int lane = t & 31;
    const int b    = blockIdx.y;
    const int pix0 = blockIdx.x * MPX;
    const int wm   = wid & 1;    // m-group: 32 px
    const int wn   = wid >> 1;   // n-group: 32 oc

    const float* xTb = g_xT + (size_t)b * HW * C1;

    float acc[2][4][4];
#pragma unroll
    for (int mt = 0; mt < 2; mt++)
#pragma unroll
        for (int j = 0; j < 4; j++)
#pragma unroll
            for (int r = 0; r < 4; r++) acc[mt][j][r] = 0.f;

    if (t < 128) s_bias[t] = bias[t];

    // ldmatrix lane addressing (constant across taps)
    const int tile = lane >> 3;
    const int rr   = ((tile & 1) << 3) + (lane & 7);
    const int cbm  = (tile >> 1) << 3;

    // ---- per-warp register meta: lane l8 handles px = pix0 + wid*8 + l8 ----
    const int l8     = lane & 7;
    const int pxm    = pix0 + wid * 8 + l8;
    const int hom    = pxm / Ww;
    const int wom    = pxm - hom * Ww;
    float m_w0, m_w1, m_w2, m_w3;
    int   m_o0, m_o1, m_o2, m_o3;

    auto compute_meta = [&](int tap) {
        const int ki = tap / 3;
        const int kj = tap % 3;
        float dy = g_offset[(b * OFFC + 2 * tap) * HW + pxm];
        float dx = g_offset[(b * OFFC + 2 * tap + 1) * HW + pxm];
        float py  = (float)(hom - 1 + ki) + dy;
        float pxx = (float)(wom - 1 + kj) + dx;
        float y0 = floorf(py);
        float x0 = floorf(pxx);
        float wy1 = py - y0, wy0 = 1.f - wy1;
        float wx1 = pxx - x0, wx0 = 1.f - wx1;

        float yc0 = y0, yc1 = y0 + 1.f, xc0 = x0, xc1 = x0 + 1.f;
        bool vy0 = (yc0 >= 0.f) && (yc0 < (float)Hh);
        bool vy1 = (yc1 >= 0.f) && (yc1 < (float)Hh);
        bool vx0 = (xc0 >= 0.f) && (xc0 < (float)Ww);
        bool vx1 = (xc1 >= 0.f) && (xc1 < (float)Ww);
        int iy0 = (int)fminf(fmaxf(yc0, 0.f), (float)(Hh - 1));
        int iy1 = (int)fminf(fmaxf(yc1, 0.f), (float)(Hh - 1));
        int ix0 = (int)fminf(fmaxf(xc0, 0.f), (float)(Ww - 1));
        int ix1 = (int)fminf(fmaxf(xc1, 0.f), (float)(Ww - 1));
        m_w0 = (vy0 && vx0) ? wy0 * wx0 : 0.f;  m_o0 = iy0 * Ww + ix0;
        m_w1 = (vy0 && vx1) ? wy0 * wx1 : 0.f;  m_o1 = iy0 * Ww + ix1;
        m_w2 = (vy1 && vx0) ? wy1 * wx0 : 0.f;  m_o2 = iy1 * Ww + ix0;
        m_w3 = (vy1 && vx1) ? wy1 * wx1 : 0.f;  m_o3 = iy1 * Ww + ix1;
    };

    auto gather_into = [&](int bufsel) {
        __nv_bfloat16* Ah = reinterpret_cast<__nv_bfloat16*>(
            smem + (bufsel ? SMO_BUF1 : SMO_BUF0));
        __nv_bfloat16* Al = reinterpret_cast<__nv_bfloat16*>(
            smem + (bufsel ? SMO_BUF1 : SMO_BUF0) + ABYTES);
        const int pxbase = wid * 8;
#pragma unroll 2
        for (int i = 0; i < 8; i++) {
            const int px = pxbase + i;
            const float w0 = __shfl_sync(0xffffffffu, m_w0, i);
            const float w1 = __shfl_sync(0xffffffffu, m_w1, i);
            const float w2 = __shfl_sync(0xffffffffu, m_w2, i);
            const float w3 = __shfl_sync(0xffffffffu, m_w3, i);
            const int o0 = __shfl_sync(0xffffffffu, m_o0, i);
            const int o1 = __shfl_sync(0xffffffffu, m_o1, i);
            const int o2 = __shfl_sync(0xffffffffu, m_o2, i);
            const int o3 = __shfl_sync(0xffffffffu, m_o3, i);
            const float4* p0 = reinterpret_cast<const float4*>(
                xTb + (size_t)o0 * C1) + lane;
            const float4* p1 = reinterpret_cast<const float4*>(
                xTb + (size_t)o1 * C1) + lane;
            const float4* p2 = reinterpret_cast<const float4*>(
                xTb + (size_t)o2 * C1) + lane;
            const float4* p3 = reinterpret_cast<const float4*>(
                xTb + (size_t)o3 * C1) + lane;
            float4 v0 = *p0, v1 = *p1, v2 = *p2, v3 = *p3;
            float ax = w0 * v0.x; ax = fmaf(w1, v1.x, ax);
            ax = fmaf(w2, v2.x, ax); ax = fmaf(w3, v3.x, ax);
            float ay = w0 * v0.y; ay = fmaf(w1, v1.y, ay);
            ay = fmaf(w2, v2.y, ay); ay = fmaf(w3, v3.y, ay);
            float az = w0 * v0.z; az = fmaf(w1, v1.z, az);
            az = fmaf(w2, v2.z, az); az = fmaf(w3, v3.z, az);
            float aw = w0 * v0.w; aw = fmaf(w1, v1.w, aw);
            aw = fmaf(w2, v2.w, aw); aw = fmaf(w3, v3.w, aw);
            uint32_t lo0, lo1;
            uint32_t hi0 = split_pack2(ax, ay, lo0);
            uint32_t hi1 = split_pack2(az, aw, lo1);
            *reinterpret_cast<uint2*>(Ah + px * LDA + lane * 4) = make_uint2(hi0, hi1);
            *reinterpret_cast<uint2*>(Al + px * LDA + lane * 4) = make_uint2(lo0, lo1);
        }
    };

    // ---- prologue: fill buffer 0 for tap 0 ----
    compute_meta(0);
    gather_into(0);
    __syncthreads();

    // ---- pipelined main loop: 1 sync per tap ----
#pragma unroll 1
    for (int tap = 0; tap < 9; tap++) {
        const int cur = tap & 1;
        if (tap < 8) {
            compute_meta(tap + 1);
            gather_into(1 - cur);
        }

        // MMA(tap) on buf[cur]
        const uint32_t abase = sb + (cur ? SMO_BUF1 : SMO_BUF0);
        const int m0 = wm * 32;
#pragma unroll 1
        for (int kc = 0; kc < 8; kc++) {
            uint32_t bh[4][2], bl[4][2];
            const uint4* wf = g_wF + (((size_t)tap * 8 + kc) * 16 + wn * 4) * 32 + lane;
#pragma unroll
            for (int j = 0; j < 4; j++) {
                uint4 bv = wf[j * 32];
                bh[j][0] = bv.x; bh[j][1] = bv.y;
                bl[j][0] = bv.z; bl[j][1] = bv.w;
            }
            uint32_t ah[2][4], al[2][4];
#pragma unroll
            for (int mt = 0; mt < 2; mt++) {
                uint32_t off = ((m0 + mt * 16 + rr) * LDA + kc * 16 + cbm) * 2;
                ldsm_x4(ah[mt], abase + off);
                ldsm_x4(al[mt], abase + ABYTES + off);
            }
#pragma unroll
            for (int mt = 0; mt < 2; mt++) {
#pragma unroll
                for (int j = 0; j < 4; j++) {
                    mma16816(acc[mt][j], ah[mt], bh[j]);
                    mma16816(acc[mt][j], ah[mt], bl[j]);
                    mma16816(acc[mt][j], al[mt], bh[j]);
                }
            }
        }
        __syncthreads();
    }

    // ---- epilogue: D frags -> smem [px][oc] -> coalesced gmem ----
    {
        const int r0 = lane >> 2;
        const int c0 = (lane & 3) * 2;
#pragma unroll
        for (int mt = 0; mt < 2; mt++) {
#pragma unroll
            for (int j = 0; j < 4; j++) {
                const int row = wm * 32 + mt * 16 + r0;
                const int col = wn * 32 + j * 8 + c0;
                *reinterpret_cast<float2*>(s_out + row * LDO + col) =
                    make_float2(acc[mt][j][0], acc[mt][j][1]);
                *reinterpret_cast<float2*>(s_out + (row + 8) * LDO + col) =
                    make_float2(acc[mt][j][2], acc[mt][j][3]);
            }
        }
    }
    __syncthreads();

#pragma unroll 4
    for (int j = 0; j < 32; j++) {
        int i  = t + 256 * j;   // 8192 outputs
        int oc = i >> 6;
        int px = i & 63;
        out[(size_t)(b * C2 + oc) * HW + pix0 + px] =
            s_out[px * LDO + oc] + s_bias[oc];
    }
}

// ============================================================================
extern "C" void kernel_launch(void* const* d_in, const int* in_sizes, int n_in,
                              void* d_out, int out_size) {
    const float* x    = (const float*)d_in[0];
    const float* ow   = (const float*)d_in[1];
    const float* ob   = (const float*)d_in[2];
    const float* wgt  = (const float*)d_in[3];
    const float* bias = (const float*)d_in[4];
    float* out = (float*)d_out;

    dim3 gn(Hh, BATCH);
    nhwc_kernel<<<gn, 256>>>(x);

    prep_wfrag_kernel<<<(9 * 8 * 16 * 32 + 255) / 256, 256>>>(wgt);

    dim3 g1(Ww / OT, Hh / OT, BATCH);
    offset_conv_kernel<<<g1, 256>>>(x, ow, ob);

    cudaFuncSetAttribute(deform_mma_kernel,
                         cudaFuncAttributeMaxDynamicSharedMemorySize,
                         SMEM_TOTAL_D);
    dim3 g2(HW / MPX, BATCH);
    deform_mma_kernel<<<g2, 256, SMEM_TOTAL_D>>>(bias, out);
}

// round 8
// speedup vs baseline: 2.6126x; 1.2433x over previous
#include <cuda_runtime.h>
#include <cuda_fp16.h>
#include <cstdint>

// ---------------------------------------------------------------------------
// DSConv2d: offset conv (3x3, 128->18) + deformable conv (3x3, 128->128)
// B=16, C1=C2=128, H=W=80, fp32.
// Deform conv: NHWC gather (fp32) -> fp16 implicit GEMM, single-term
// mma.m16n8k16 (validated error model: rel_err ~4e-4 < 1e-3).
// ---------------------------------------------------------------------------

#define Hh 80
#define Ww 80
#define HW 6400
#define C1 128
#define C2 128
#define BATCH 16
#define OFFC 18

static __device__ float g_offset[BATCH * OFFC * HW];   // 7.37 MB
static __device__ float g_xT[BATCH * HW * C1];         // 52.4 MB NHWC
static __device__ uint2 g_wF[9 * 8 * 16 * 32];         // frag-packed fp16 weights

// ============================================================================
// Kernel 0a: NCHW -> NHWC transform of x
// ============================================================================
__global__ __launch_bounds__(256) void nhwc_kernel(const float* __restrict__ x)
{
    __shared__ float tile[128][81];
    const int h = blockIdx.x;
    const int b = blockIdx.y;
    const int t = threadIdx.x;

    for (int idx = t; idx < 128 * 80; idx += 256) {
        int c = idx / 80;
        int w = idx - c * 80;
        tile[c][w] = x[((size_t)(b * C1 + c) * Hh + h) * Ww + w];
    }
    __syncthreads();
    for (int idx = t; idx < 80 * 128; idx += 256) {
        int w = idx >> 7;
        int c = idx & 127;
        g_xT[((size_t)b * HW + h * Ww + w) * C1 + c] = tile[c][w];
    }
}

// ============================================================================
// Kernel 0b: weight -> mma.m16n8k16 B-fragment packing, fp16.
// B matrix for tap: B[k=c][n=oc] = wgt[oc][c][tap].
// Fragment (kc,nf): lane holds {b[kb][n],b[kb+1][n]} , {b[kb+8][n],b[kb+9][n]}
// with n = nf*8 + lane/4, kb = kc*16 + (lane%4)*2.
// ============================================================================
__global__ __launch_bounds__(256) void prep_wfrag_kernel(const float* __restrict__ wgt)
{
    int i = blockIdx.x * 256 + threadIdx.x;
    if (i >= 9 * 8 * 16 * 32) return;
    int lane = i & 31;
    int nf   = (i >> 5) & 15;
    int kc   = (i >> 9) & 7;
    int tap  = i >> 12;
    int n  = nf * 8 + (lane >> 2);
    int kb = kc * 16 + (lane & 3) * 2;

    __half h00 = __float2half_rn(wgt[(n * 128 + kb + 0) * 9 + tap]);
    __half h01 = __float2half_rn(wgt[(n * 128 + kb + 1) * 9 + tap]);
    __half h10 = __float2half_rn(wgt[(n * 128 + kb + 8) * 9 + tap]);
    __half h11 = __float2half_rn(wgt[(n * 128 + kb + 9) * 9 + tap]);

    uint2 v;
    v.x = ((uint32_t)__half_as_ushort(h01) << 16) | (uint32_t)__half_as_ushort(h00);
    v.y = ((uint32_t)__half_as_ushort(h11) << 16) | (uint32_t)__half_as_ushort(h10);
    g_wF[i] = v;
}

// ============================================================================
// Kernel 1: offset conv (verified numerics, unchanged — near fp32 SIMT floor)
// ============================================================================
#define OT 16
#define OCC 16

__global__ __launch_bounds__(256) void offset_conv_kernel(
    const float* __restrict__ x,
    const float* __restrict__ ow,
    const float* __restrict__ ob)
{
    __shared__ float xs[OCC][18][18];
    __shared__ float ws[OCC * 9][20];

    const int b   = blockIdx.z;
    const int by0 = blockIdx.y * OT;
    const int bx0 = blockIdx.x * OT;
    const int t   = threadIdx.x;
    const int tx  = t & 15;
    const int ty  = t >> 4;

    float acc[18];
#pragma unroll
    for (int i = 0; i < 18; i++) acc[i] = 0.f;

    for (int cb = 0; cb < C1; cb += OCC) {
        __syncthreads();
        for (int i = t; i < OCC * 18 * 18; i += 256) {
            int c   = i / 324;
            int rem = i - c * 324;
            int r   = rem / 18;
            int col = rem - r * 18;
            int y   = by0 - 1 + r;
            int xx  = bx0 - 1 + col;
            float v = 0.f;
            if (y >= 0 && y < Hh && xx >= 0 && xx < Ww)
                v = x[(b * C1 + cb + c) * HW + y * Ww + xx];
            xs[c][r][col] = v;
        }
        for (int i = t; i < 18 * 36; i += 256) {
            int oc = i / 36;
            int q  = i - oc * 36;
            float4 v = *reinterpret_cast<const float4*>(ow + oc * (C1 * 9) + cb * 9 + q * 4);
            int k = q * 4;
            ws[k + 0][oc] = v.x;
            ws[k + 1][oc] = v.y;
            ws[k + 2][oc] = v.z;
            ws[k + 3][oc] = v.w;
        }
        __syncthreads();

#pragma unroll 1
        for (int c = 0; c < OCC; c++) {
#pragma unroll
            for (int tap = 0; tap < 9; tap++) {
                const int ki = tap / 3;
                const int kj = tap % 3;
                float xv = xs[c][ty + ki][tx + kj];
                const float* wp = &ws[c * 9 + tap][0];
                float wreg[18];
                float4 w0 = *reinterpret_cast<const float4*>(wp);
                float4 w1 = *reinterpret_cast<const float4*>(wp + 4);
                float4 w2 = *reinterpret_cast<const float4*>(wp + 8);
                float4 w3 = *reinterpret_cast<const float4*>(wp + 12);
                wreg[0] = w0.x;  wreg[1] = w0.y;  wreg[2] = w0.z;  wreg[3] = w0.w;
                wreg[4] = w1.x;  wreg[5] = w1.y;  wreg[6] = w1.z;  wreg[7] = w1.w;
                wreg[8] = w2.x;  wreg[9] = w2.y;  wreg[10] = w2.z; wreg[11] = w2.w;
                wreg[12] = w3.x; wreg[13] = w3.y; wreg[14] = w3.z; wreg[15] = w3.w;
                wreg[16] = wp[16]; wreg[17] = wp[17];
#pragma unroll
                for (int j = 0; j < 18; j++)
                    acc[j] = fmaf(xv, wreg[j], acc[j]);
            }
        }
    }

    const int pix = (by0 + ty) * Ww + bx0 + tx;
#pragma unroll
    for (int ch = 0; ch < 18; ch++)
        g_offset[(b * OFFC + ch) * HW + pix] = acc[ch] + ob[ch];
}

// ============================================================================
// Kernel 2: deformable conv. 64px x 128oc, 3 CTAs/SM, software-pipelined.
// Single fp16 A matrix double-buffered; register meta; frag-packed fp16 B;
// one mma term per (mt,nf,kc).
// ============================================================================
#define MPX 64
#define LDA 136   // fp16 elements per A row (272B, conflict-free ldmatrix)
#define LDO 132

#define SMO_BIAS 0
#define SMO_BUF0 1024
#define ABYTES   (MPX * LDA * 2)          // 17408 per buffer
#define SMO_BUF1 (SMO_BUF0 + ABYTES)      // 18432
#define SMEM_TOTAL_D (SMO_BUF1 + ABYTES)  // 35840

__device__ __forceinline__ uint32_t smem_u32(const void* p) {
    uint32_t a;
    asm("{ .reg .u64 t; cvta.to.shared.u64 t, %1; cvt.u32.u64 %0, t; }"
        : "=r"(a) : "l"(p));
    return a;
}

__device__ __forceinline__ void ldsm_x4(uint32_t* r, uint32_t saddr) {
    asm volatile("ldmatrix.sync.aligned.m8n8.x4.shared.b16 {%0,%1,%2,%3}, [%4];"
                 : "=r"(r[0]), "=r"(r[1]), "=r"(r[2]), "=r"(r[3])
                 : "r"(saddr));
}

__device__ __forceinline__ void mma16816h(float* d, const uint32_t* a,
                                          const uint32_t* b) {
    asm volatile(
        "mma.sync.aligned.m16n8k16.row.col.f32.f16.f16.f32 "
        "{%0,%1,%2,%3}, {%4,%5,%6,%7}, {%8,%9}, {%0,%1,%2,%3};"
        : "+f"(d[0]), "+f"(d[1]), "+f"(d[2]), "+f"(d[3])
        : "r"(a[0]), "r"(a[1]), "r"(a[2]), "r"(a[3]),
          "r"(b[0]), "r"(b[1]));
}

__global__ __launch_bounds__(256, 3)
void deform_mma_kernel(const float* __restrict__ bias,
                       float* __restrict__ out)
{
    extern __shared__ char smem[];
    const uint32_t sb = smem_u32(smem);
    float* s_bias = reinterpret_cast<float*>(smem + SMO_BIAS);
    float* s_out  = reinterpret_cast<float*>(smem + SMO_BUF0);  // reuse post-MMA

    const int t    = threadIdx.x;
    const int wid  = t >> 5;
    const int lane = t & 31;
    const int b    = blockIdx.y;
    const int pix0 = blockIdx.x * MPX;
    const int wm   = wid & 1;    // m-group: 32 px
    const int wn   = wid >> 1;   // n-group: 32 oc

    const float* xTb = g_xT + (size_t)b * HW * C1;

    float acc[2][4][4];
#pragma unroll
    for (int mt = 0; mt < 2; mt++)
#pragma unroll
        for (int j = 0; j < 4; j++)
#pragma unroll
            for (int r = 0; r < 4; r++) acc[mt][j][r] = 0.f;

    if (t < 128) s_bias[t] = bias[t];

    // ldmatrix lane addressing (constant across taps)
    const int tile = lane >> 3;
    const int rr   = ((tile & 1) << 3) + (lane & 7);
    const int cbm  = (tile >> 1) << 3;

    // ---- per-warp register meta: lane l8 handles px = pix0 + wid*8 + l8 ----
    const int l8     = lane & 7;
    const int pxm    = pix0 + wid * 8 + l8;
    const int hom    = pxm / Ww;
    const int wom    = pxm - hom * Ww;
    float m_w0, m_w1, m_w2, m_w3;
    int   m_o0, m_o1, m_o2, m_o3;

    auto compute_meta = [&](int tap) {
        const int ki = tap / 3;
        const int kj = tap % 3;
        float dy = g_offset[(b * OFFC + 2 * tap) * HW + pxm];
        float dx = g_offset[(b * OFFC + 2 * tap + 1) * HW + pxm];
        float py  = (float)(hom - 1 + ki) + dy;
        float pxx = (float)(wom - 1 + kj) + dx;
        float y0 = floorf(py);
        float x0 = floorf(pxx);
        float wy1 = py - y0, wy0 = 1.f - wy1;
        float wx1 = pxx - x0, wx0 = 1.f - wx1;

        float yc0 = y0, yc1 = y0 + 1.f, xc0 = x0, xc1 = x0 + 1.f;
        bool vy0 = (yc0 >= 0.f) && (yc0 < (float)Hh);
        bool vy1 = (yc1 >= 0.f) && (yc1 < (float)Hh);
        bool vx0 = (xc0 >= 0.f) && (xc0 < (float)Ww);
        bool vx1 = (xc1 >= 0.f) && (xc1 < (float)Ww);
        int iy0 = (int)fminf(fmaxf(yc0, 0.f), (float)(Hh - 1));
        int iy1 = (int)fminf(fmaxf(yc1, 0.f), (float)(Hh - 1));
        int ix0 = (int)fminf(fmaxf(xc0, 0.f), (float)(Ww - 1));
        int ix1 = (int)fminf(fmaxf(xc1, 0.f), (float)(Ww - 1));
        m_w0 = (vy0 && vx0) ? wy0 * wx0 : 0.f;  m_o0 = iy0 * Ww + ix0;
        m_w1 = (vy0 && vx1) ? wy0 * wx1 : 0.f;  m_o1 = iy0 * Ww + ix1;
        m_w2 = (vy1 && vx0) ? wy1 * wx0 : 0.f;  m_o2 = iy1 * Ww + ix0;
        m_w3 = (vy1 && vx1) ? wy1 * wx1 : 0.f;  m_o3 = iy1 * Ww + ix1;
    };

    auto gather_into = [&](int bufsel) {
        __half* Ah = reinterpret_cast<__half*>(
            smem + (bufsel ? SMO_BUF1 : SMO_BUF0));
        const int pxbase = wid * 8;
#pragma unroll 2
        for (int i = 0; i < 8; i++) {
            const int px = pxbase + i;
            const float w0 = __shfl_sync(0xffffffffu, m_w0, i);
            const float w1 = __shfl_sync(0xffffffffu, m_w1, i);
            const float w2 = __shfl_sync(0xffffffffu, m_w2, i);
            const float w3 = __shfl_sync(0xffffffffu, m_w3, i);
            const int o0 = __shfl_sync(0xffffffffu, m_o0, i);
            const int o1 = __shfl_sync(0xffffffffu, m_o1, i);
            const int o2 = __shfl_sync(0xffffffffu, m_o2, i);
            const int o3 = __shfl_sync(0xffffffffu, m_o3, i);
            const float4* p0 = reinterpret_cast<const float4*>(
                xTb + (size_t)o0 * C1) + lane;
            const float4* p1 = reinterpret_cast<const float4*>(
                xTb + (size_t)o1 * C1) + lane;
            const float4* p2 = reinterpret_cast<const float4*>(
                xTb + (size_t)o2 * C1) + lane;
            const float4* p3 = reinterpret_cast<const float4*>(
                xTb + (size_t)o3 * C1) + lane;
            float4 v0 = *p0, v1 = *p1, v2 = *p2, v3 = *p3;
            float ax = w0 * v0.x; ax = fmaf(w1, v1.x, ax);
            ax = fmaf(w2, v2.x, ax); ax = fmaf(w3, v3.x, ax);
            float ay = w0 * v0.y; ay = fmaf(w1, v1.y, ay);
            ay = fmaf(w2, v2.y, ay); ay = fmaf(w3, v3.y, ay);
            float az = w0 * v0.z; az = fmaf(w1, v1.z, az);
            az = fmaf(w2, v2.z, az); az = fmaf(w3, v3.z, az);
            float aw = w0 * v0.w; aw = fmaf(w1, v1.w, aw);
            aw = fmaf(w2, v2.w, aw); aw = fmaf(w3, v3.w, aw);
            __half2 h01 = __floats2half2_rn(ax, ay);
            __half2 h23 = __floats2half2_rn(az, aw);
            uint2 pk;
            pk.x = *reinterpret_cast<uint32_t*>(&h01);
            pk.y = *reinterpret_cast<uint32_t*>(&h23);
            *reinterpret_cast<uint2*>(Ah + px * LDA + lane * 4) = pk;
        }
    };

    // ---- prologue: fill buffer 0 for tap 0 ----
    compute_meta(0);
    gather_into(0);
    __syncthreads();

    // ---- pipelined main loop: 1 sync per tap ----
#pragma unroll 1
    for (int tap = 0; tap < 9; tap++) {
        const int cur = tap & 1;
        if (tap < 8) {
            compute_meta(tap + 1);
            gather_into(1 - cur);
        }

        // MMA(tap) on buf[cur]
        const uint32_t abase = sb + (cur ? SMO_BUF1 : SMO_BUF0);
        const int m0 = wm * 32;
#pragma unroll 1
        for (int kc = 0; kc < 8; kc++) {
            uint32_t bf[4][2];
            const uint2* wf = g_wF + (((size_t)tap * 8 + kc) * 16 + wn * 4) * 32 + lane;
#pragma unroll
            for (int j = 0; j < 4; j++) {
                uint2 bv = wf[j * 32];
                bf[j][0] = bv.x; bf[j][1] = bv.y;
            }
            uint32_t af[2][4];
#pragma unroll
            for (int mt = 0; mt < 2; mt++) {
                uint32_t off = ((m0 + mt * 16 + rr) * LDA + kc * 16 + cbm) * 2;
                ldsm_x4(af[mt], abase + off);
            }
#pragma unroll
            for (int mt = 0; mt < 2; mt++) {
#pragma unroll
                for (int j = 0; j < 4; j++) {
                    mma16816h(acc[mt][j], af[mt], bf[j]);
                }
            }
        }
        __syncthreads();
    }

    // ---- epilogue: D frags -> smem [px][oc] -> coalesced gmem ----
    {
        const int r0 = lane >> 2;
        const int c0 = (lane & 3) * 2;
#pragma unroll
        for (int mt = 0; mt < 2; mt++) {
#pragma unroll
            for (int j = 0; j < 4; j++) {
                const int row = wm * 32 + mt * 16 + r0;
                const int col = wn * 32 + j * 8 + c0;
                *reinterpret_cast<float2*>(s_out + row * LDO + col) =
                    make_float2(acc[mt][j][0], acc[mt][j][1]);
                *reinterpret_cast<float2*>(s_out + (row + 8) * LDO + col) =
                    make_float2(acc[mt][j][2], acc[mt][j][3]);
            }
        }
    }
    __syncthreads();

#pragma unroll 4
    for (int j = 0; j < 32; j++) {
        int i  = t + 256 * j;   // 8192 outputs
        int oc = i >> 6;
        int px = i & 63;
        out[(size_t)(b * C2 + oc) * HW + pix0 + px] =
            s_out[px * LDO + oc] + s_bias[oc];
    }
}

// ============================================================================
extern "C" void kernel_launch(void* const* d_in, const int* in_sizes, int n_in,
                              void* d_out, int out_size) {
    const float* x    = (const float*)d_in[0];
    const float* ow   = (const float*)d_in[1];
    const float* ob   = (const float*)d_in[2];
    const float* wgt  = (const float*)d_in[3];
    const float* bias = (const float*)d_in[4];
    float* out = (float*)d_out;

    dim3 gn(Hh, BATCH);
    nhwc_kernel<<<gn, 256>>>(x);

    prep_wfrag_kernel<<<(9 * 8 * 16 * 32 + 255) / 256, 256>>>(wgt);

    dim3 g1(Ww / OT, Hh / OT, BATCH);
    offset_conv_kernel<<<g1, 256>>>(x, ow, ob);

    cudaFuncSetAttribute(deform_mma_kernel,
                         cudaFuncAttributeMaxDynamicSharedMemorySize,
                         SMEM_TOTAL_D);
    dim3 g2(HW / MPX, BATCH);
    deform_mma_kernel<<<g2, 256, SMEM_TOTAL_D>>>(bias, out);
}

// round 9
// speedup vs baseline: 3.1988x; 1.2244x over previous
#include <cuda_runtime.h>
#include <cuda_fp16.h>
#include <cstdint>

// ---------------------------------------------------------------------------
// DSConv2d: offset conv (3x3, 128->18) + deformable conv (3x3, 128->128)
// B=16, C1=C2=128, H=W=80, fp32.
// Round 9: fp16 NHWC x for deform gather; tensor-core offset conv
// (fp16 3-term hi/lo split, N padded 18->24).
// ---------------------------------------------------------------------------

#define Hh 80
#define Ww 80
#define HW 6400
#define C1 128
#define C2 128
#define BATCH 16
#define OFFC 18

static __device__ float  g_offset[BATCH * OFFC * HW];   // 7.37 MB
static __device__ float  g_xT[BATCH * HW * C1];         // 52.4 MB NHWC fp32
static __device__ __half g_xTh[BATCH * HW * C1];        // 26.2 MB NHWC fp16
static __device__ uint2  g_wF[9 * 8 * 16 * 32];         // deform B frags (fp16)
static __device__ uint4  g_oF[9 * 8 * 3 * 32];          // offset B frags (fp16 hi/lo)

// ============================================================================
// common helpers
// ============================================================================
__device__ __forceinline__ uint32_t smem_u32(const void* p) {
    uint32_t a;
    asm("{ .reg .u64 t; cvta.to.shared.u64 t, %1; cvt.u32.u64 %0, t; }"
        : "=r"(a) : "l"(p));
    return a;
}

__device__ __forceinline__ void ldsm_x4(uint32_t* r, uint32_t saddr) {
    asm volatile("ldmatrix.sync.aligned.m8n8.x4.shared.b16 {%0,%1,%2,%3}, [%4];"
                 : "=r"(r[0]), "=r"(r[1]), "=r"(r[2]), "=r"(r[3])
                 : "r"(saddr));
}

__device__ __forceinline__ void mma16816h(float* d, const uint32_t* a,
                                          const uint32_t* b) {
    asm volatile(
        "mma.sync.aligned.m16n8k16.row.col.f32.f16.f16.f32 "
        "{%0,%1,%2,%3}, {%4,%5,%6,%7}, {%8,%9}, {%0,%1,%2,%3};"
        : "+f"(d[0]), "+f"(d[1]), "+f"(d[2]), "+f"(d[3])
        : "r"(a[0]), "r"(a[1]), "r"(a[2]), "r"(a[3]),
          "r"(b[0]), "r"(b[1]));
}

// fp16 hi/lo split of two floats -> packed hi pair + lo pair
__device__ __forceinline__ uint32_t hsplit2(float va, float vb, uint32_t& lo) {
    __half ha = __float2half_rn(va);
    __half hb = __float2half_rn(vb);
    __half la = __float2half_rn(va - __half2float(ha));
    __half lb = __float2half_rn(vb - __half2float(hb));
    lo = ((uint32_t)__half_as_ushort(lb) << 16) | (uint32_t)__half_as_ushort(la);
    return ((uint32_t)__half_as_ushort(hb) << 16) | (uint32_t)__half_as_ushort(ha);
}

// ============================================================================
// Kernel 0a: NCHW -> NHWC (fp32 + fp16)
// ============================================================================
__global__ __launch_bounds__(256) void nhwc_kernel(const float* __restrict__ x)
{
    __shared__ float tile[128][81];
    const int h = blockIdx.x;
    const int b = blockIdx.y;
    const int t = threadIdx.x;

    for (int idx = t; idx < 128 * 80; idx += 256) {
        int c = idx / 80;
        int w = idx - c * 80;
        tile[c][w] = x[((size_t)(b * C1 + c) * Hh + h) * Ww + w];
    }
    __syncthreads();
    for (int idx = t; idx < 80 * 128; idx += 256) {
        int w = idx >> 7;
        int c = idx & 127;
        float v = tile[c][w];
        size_t o = ((size_t)b * HW + h * Ww + w) * C1 + c;
        g_xT[o]  = v;
        g_xTh[o] = __float2half_rn(v);
    }
}

// ============================================================================
// Kernel 0b: deform weights -> m16n8k16 B frags, fp16 single-term
// ============================================================================
__global__ __launch_bounds__(256) void prep_wfrag_kernel(const float* __restrict__ wgt)
{
    int i = blockIdx.x * 256 + threadIdx.x;
    if (i >= 9 * 8 * 16 * 32) return;
    int lane = i & 31;
    int nf   = (i >> 5) & 15;
    int kc   = (i >> 9) & 7;
    int tap  = i >> 12;
    int n  = nf * 8 + (lane >> 2);
    int kb = kc * 16 + (lane & 3) * 2;

    __half h00 = __float2half_rn(wgt[(n * 128 + kb + 0) * 9 + tap]);
    __half h01 = __float2half_rn(wgt[(n * 128 + kb + 1) * 9 + tap]);
    __half h10 = __float2half_rn(wgt[(n * 128 + kb + 8) * 9 + tap]);
    __half h11 = __float2half_rn(wgt[(n * 128 + kb + 9) * 9 + tap]);

    uint2 v;
    v.x = ((uint32_t)__half_as_ushort(h01) << 16) | (uint32_t)__half_as_ushort(h00);
    v.y = ((uint32_t)__half_as_ushort(h11) << 16) | (uint32_t)__half_as_ushort(h10);
    g_wF[i] = v;
}

// ============================================================================
// Kernel 0c: offset weights -> B frags, fp16 hi/lo (3-term split), N pad 18->24
// B[k=c][n] = ow[n][c][tap];  n >= 18 -> 0.
// ============================================================================
__global__ __launch_bounds__(256) void prep_ofrag_kernel(const float* __restrict__ ow)
{
    int i = blockIdx.x * 256 + threadIdx.x;
    if (i >= 9 * 8 * 3 * 32) return;
    int lane = i & 31;
    int nf   = (i >> 5) % 3;
    int kc   = (i >> 5) / 3 % 8;
    int tap  = (i >> 5) / 24;
    int n  = nf * 8 + (lane >> 2);
    int kb = kc * 16 + (lane & 3) * 2;

    float w00 = 0.f, w01 = 0.f, w10 = 0.f, w11 = 0.f;
    if (n < OFFC) {
        w00 = ow[(n * 128 + kb + 0) * 9 + tap];
        w01 = ow[(n * 128 + kb + 1) * 9 + tap];
        w10 = ow[(n * 128 + kb + 8) * 9 + tap];
        w11 = ow[(n * 128 + kb + 9) * 9 + tap];
    }
    uint4 v;
    uint32_t l01, l89;
    v.x = hsplit2(w00, w01, l01);
    v.y = hsplit2(w10, w11, l89);
    v.z = l01;
    v.w = l89;
    g_oF[i] = v;
}

// ============================================================================
// Kernel 1: offset conv via tensor cores.
// Block = 128 px, N = 24 (18 real), K = 1152 (9 taps x 8 kc).
// A = fixed 3x3-window NHWC fp32 rows, split fp16 hi/lo; 3-term MMA.
// 8 warps x 16 px. Single A buffer, 2 syncs/tap, 2 CTAs/SM.
// ============================================================================
#define OLDA 136
#define OABYTES (128 * OLDA * 2)              // 34816 per matrix
#define OSM_OB   0
#define OSM_AH   1024
#define OSM_AL   (OSM_AH + OABYTES)
#define OSMEM_TOTAL (OSM_AL + OABYTES)        // 70656
#define LDOF 28

__global__ __launch_bounds__(256, 2)
void offset_mma_kernel(const float* __restrict__ ob)
{
    extern __shared__ char smem[];
    const uint32_t sb = smem_u32(smem);
    float* s_ob  = reinterpret_cast<float*>(smem + OSM_OB);
    float* s_out = reinterpret_cast<float*>(smem + OSM_AH);  // reuse post-MMA

    const int t    = threadIdx.x;
    const int wid  = t >> 5;
    const int lane = t & 31;
    const int b    = blockIdx.y;
    const int pix0 = blockIdx.x * 128;

    const float* xTb = g_xT + (size_t)b * HW * C1;

    if (t < OFFC) s_ob[t] = ob[t];

    float acc[3][4];
#pragma unroll
    for (int j = 0; j < 3; j++)
#pragma unroll
        for (int r = 0; r < 4; r++) acc[j][r] = 0.f;

    // ldmatrix lane addressing
    const int tile = lane >> 3;
    const int rr   = ((tile & 1) << 3) + (lane & 7);
    const int cbm  = (tile >> 1) << 3;
    const int m0   = wid * 16;

#pragma unroll 1
    for (int tap = 0; tap < 9; tap++) {
        const int ki = tap / 3;
        const int kj = tap % 3;

        // ---- A: fixed-window NHWC fp32 rows -> fp16 hi/lo smem ----
        {
            __half* Ah = reinterpret_cast<__half*>(smem + OSM_AH);
            __half* Al = reinterpret_cast<__half*>(smem + OSM_AL);
#pragma unroll 2
            for (int i = 0; i < 16; i++) {
                const int px  = m0 + i;
                const int pix = pix0 + px;
                const int ho  = pix / Ww;
                const int wo  = pix - ho * Ww;
                const int sy  = ho - 1 + ki;
                const int sx  = wo - 1 + kj;
                uint32_t h01 = 0, h23 = 0, l01 = 0, l23 = 0;
                if (sy >= 0 && sy < Hh && sx >= 0 && sx < Ww) {
                    const float4 v = *(reinterpret_cast<const float4*>(
                        xTb + (size_t)(sy * Ww + sx) * C1) + lane);
                    h01 = hsplit2(v.x, v.y, l01);
                    h23 = hsplit2(v.z, v.w, l23);
                }
                *reinterpret_cast<uint2*>(Ah + px * OLDA + lane * 4) = make_uint2(h01, h23);
                *reinterpret_cast<uint2*>(Al + px * OLDA + lane * 4) = make_uint2(l01, l23);
            }
        }
        __syncthreads();

        // ---- MMA: 8 kc x 3 nfrags x 3 terms ----
#pragma unroll 1
        for (int kc = 0; kc < 8; kc++) {
            uint32_t bh[3][2], bl[3][2];
            const uint4* wf = g_oF + (((size_t)tap * 8 + kc) * 3) * 32 + lane;
#pragma unroll
            for (int j = 0; j < 3; j++) {
                uint4 bv = wf[j * 32];
                bh[j][0] = bv.x; bh[j][1] = bv.y;
                bl[j][0] = bv.z; bl[j][1] = bv.w;
            }
            uint32_t ah[4], al[4];
            uint32_t off = ((m0 + rr) * OLDA + kc * 16 + cbm) * 2;
            ldsm_x4(ah, sb + OSM_AH + off);
            ldsm_x4(al, sb + OSM_AL + off);
#pragma unroll
            for (int j = 0; j < 3; j++) {
                mma16816h(acc[j], ah, bh[j]);
                mma16816h(acc[j], ah, bl[j]);
                mma16816h(acc[j], al, bh[j]);
            }
        }
        __syncthreads();
    }

    // ---- epilogue: acc -> s_out[px][24] -> g_offset ----
    {
        const int r0 = lane >> 2;
        const int c0 = (lane & 3) * 2;
#pragma unroll
        for (int j = 0; j < 3; j++) {
            const int col = j * 8 + c0;
            *reinterpret_cast<float2*>(s_out + (m0 + r0) * LDOF + col) =
                make_float2(acc[j][0], acc[j][1]);
            *reinterpret_cast<float2*>(s_out + (m0 + r0 + 8) * LDOF + col) =
                make_float2(acc[j][2], acc[j][3]);
        }
    }
    __syncthreads();

#pragma unroll
    for (int j = 0; j < 9; j++) {
        int i  = t + 256 * j;   // 2304 outputs = 18ch x 128px
        int ch = i >> 7;
        int px = i & 127;
        g_offset[(size_t)(b * OFFC + ch) * HW + pix0 + px] =
            s_out[px * LDOF + ch] + s_ob[ch];
    }
}

// ============================================================================
// Kernel 2: deformable conv. 64px x 128oc, 3 CTAs/SM, software-pipelined.
// fp16 NHWC gather (LDG.64 rows), single fp16 A, frag-packed fp16 B.
// ============================================================================
#define MPX 64
#define LDA 136
#define LDO 132

#define SMO_BIAS 0
#define SMO_BUF0 1024
#define ABYTES   (MPX * LDA * 2)          // 17408 per buffer
#define SMO_BUF1 (SMO_BUF0 + ABYTES)
#define SMEM_TOTAL_D (SMO_BUF1 + ABYTES)  // 35840

__global__ __launch_bounds__(256, 3)
void deform_mma_kernel(const float* __restrict__ bias,
                       float* __restrict__ out)
{
    extern __shared__ char smem[];
    const uint32_t sb = smem_u32(smem);
    float* s_bias = reinterpret_cast<float*>(smem + SMO_BIAS);
    float* s_out  = reinterpret_cast<float*>(smem + SMO_BUF0);  // reuse post-MMA

    const int t    = threadIdx.x;
    const int wid  = t >> 5;
    const int lane = t & 31;
    const int b    = blockIdx.y;
    const int pix0 = blockIdx.x * MPX;
    const int wm   = wid & 1;    // m-group: 32 px
    const int wn   = wid >> 1;   // n-group: 32 oc

    const __half* xTb = g_xTh + (size_t)b * HW * C1;

    float acc[2][4][4];
#pragma unroll
    for (int mt = 0; mt < 2; mt++)
#pragma unroll
        for (int j = 0; j < 4; j++)
#pragma unroll
            for (int r = 0; r < 4; r++) acc[mt][j][r] = 0.f;

    if (t < 128) s_bias[t] = bias[t];

    // ldmatrix lane addressing
    const int tile = lane >> 3;
    const int rr   = ((tile & 1) << 3) + (lane & 7);
    const int cbm  = (tile >> 1) << 3;

    // ---- per-warp register meta: lane l8 handles px = pix0 + wid*8 + l8 ----
    const int l8     = lane & 7;
    const int pxm    = pix0 + wid * 8 + l8;
    const int hom    = pxm / Ww;
    const int wom    = pxm - hom * Ww;
    float m_w0, m_w1, m_w2, m_w3;
    int   m_o0, m_o1, m_o2, m_o3;

    auto compute_meta = [&](int tap) {
        const int ki = tap / 3;
        const int kj = tap % 3;
        float dy = g_offset[(b * OFFC + 2 * tap) * HW + pxm];
        float dx = g_offset[(b * OFFC + 2 * tap + 1) * HW + pxm];
        float py  = (float)(hom - 1 + ki) + dy;
        float pxx = (float)(wom - 1 + kj) + dx;
        float y0 = floorf(py);
        float x0 = floorf(pxx);
        float wy1 = py - y0, wy0 = 1.f - wy1;
        float wx1 = pxx - x0, wx0 = 1.f - wx1;

        float yc0 = y0, yc1 = y0 + 1.f, xc0 = x0, xc1 = x0 + 1.f;
        bool vy0 = (yc0 >= 0.f) && (yc0 < (float)Hh);
        bool vy1 = (yc1 >= 0.f) && (yc1 < (float)Hh);
        bool vx0 = (xc0 >= 0.f) && (xc0 < (float)Ww);
        bool vx1 = (xc1 >= 0.f) && (xc1 < (float)Ww);
        int iy0 = (int)fminf(fmaxf(yc0, 0.f), (float)(Hh - 1));
        int iy1 = (int)fminf(fmaxf(yc1, 0.f), (float)(Hh - 1));
        int ix0 = (int)fminf(fmaxf(xc0, 0.f), (float)(Ww - 1));
        int ix1 = (int)fminf(fmaxf(xc1, 0.f), (float)(Ww - 1));
        m_w0 = (vy0 && vx0) ? wy0 * wx0 : 0.f;  m_o0 = iy0 * Ww + ix0;
        m_w1 = (vy0 && vx1) ? wy0 * wx1 : 0.f;  m_o1 = iy0 * Ww + ix1;
        m_w2 = (vy1 && vx0) ? wy1 * wx0 : 0.f;  m_o2 = iy1 * Ww + ix0;
        m_w3 = (vy1 && vx1) ? wy1 * wx1 : 0.f;  m_o3 = iy1 * Ww + ix1;
    };

    auto gather_into = [&](int bufsel) {
        __half* Ah = reinterpret_cast<__half*>(
            smem + (bufsel ? SMO_BUF1 : SMO_BUF0));
        const int pxbase = wid * 8;
#pragma unroll 2
        for (int i = 0; i < 8; i++) {
            const int px = pxbase + i;
            const float w0 = __shfl_sync(0xffffffffu, m_w0, i);
            const float w1 = __shfl_sync(0xffffffffu, m_w1, i);
            const float w2 = __shfl_sync(0xffffffffu, m_w2, i);
            const float w3 = __shfl_sync(0xffffffffu, m_w3, i);
            const int o0 = __shfl_sync(0xffffffffu, m_o0, i);
            const int o1 = __shfl_sync(0xffffffffu, m_o1, i);
            const int o2 = __shfl_sync(0xffffffffu, m_o2, i);
            const int o3 = __shfl_sync(0xffffffffu, m_o3, i);
            uint2 r0 = *(reinterpret_cast<const uint2*>(xTb + (size_t)o0 * C1) + lane);
            uint2 r1 = *(reinterpret_cast<const uint2*>(xTb + (size_t)o1 * C1) + lane);
            uint2 r2 = *(reinterpret_cast<const uint2*>(xTb + (size_t)o2 * C1) + lane);
            uint2 r3 = *(reinterpret_cast<const uint2*>(xTb + (size_t)o3 * C1) + lane);
            float2 v0a = __half22float2(*reinterpret_cast<__half2*>(&r0.x));
            float2 v0b = __half22float2(*reinterpret_cast<__half2*>(&r0.y));
            float2 v1a = __half22float2(*reinterpret_cast<__half2*>(&r1.x));
            float2 v1b = __half22float2(*reinterpret_cast<__half2*>(&r1.y));
            float2 v2a = __half22float2(*reinterpret_cast<__half2*>(&r2.x));
            float2 v2b = __half22float2(*reinterpret_cast<__half2*>(&r2.y));
            float2 v3a = __half22float2(*reinterpret_cast<__half2*>(&r3.x));
            float2 v3b = __half22float2(*reinterpret_cast<__half2*>(&r3.y));
            float a0 = w0 * v0a.x; a0 = fmaf(w1, v1a.x, a0);
            a0 = fmaf(w2, v2a.x, a0); a0 = fmaf(w3, v3a.x, a0);
            float a1 = w0 * v0a.y; a1 = fmaf(w1, v1a.y, a1);
            a1 = fmaf(w2, v2a.y, a1); a1 = fmaf(w3, v3a.y, a1);
            float a2 = w0 * v0b.x; a2 = fmaf(w1, v1b.x, a2);
            a2 = fmaf(w2, v2b.x, a2); a2 = fmaf(w3, v3b.x, a2);
            float a3 = w0 * v0b.y; a3 = fmaf(w1, v1b.y, a3);
            a3 = fmaf(w2, v2b.y, a3); a3 = fmaf(w3, v3b.y, a3);
            __half2 h01 = __floats2half2_rn(a0, a1);
            __half2 h23 = __floats2half2_rn(a2, a3);
            uint2 pk;
            pk.x = *reinterpret_cast<uint32_t*>(&h01);
            pk.y = *reinterpret_cast<uint32_t*>(&h23);
            *reinterpret_cast<uint2*>(Ah + px * LDA + lane * 4) = pk;
        }
    };

    // ---- prologue ----
    compute_meta(0);
    gather_into(0);
    __syncthreads();

    // ---- pipelined main loop: 1 sync per tap ----
#pragma unroll 1
    for (int tap = 0; tap < 9; tap++) {
        const int cur = tap & 1;
        if (tap < 8) {
            compute_meta(tap + 1);
            gather_into(1 - cur);
        }

        const uint32_t abase = sb + (cur ? SMO_BUF1 : SMO_BUF0);
        const int m0 = wm * 32;
#pragma unroll 1
        for (int kc = 0; kc < 8; kc++) {
            uint32_t bf[4][2];
            const uint2* wf = g_wF + (((size_t)tap * 8 + kc) * 16 + wn * 4) * 32 + lane;
#pragma unroll
            for (int j = 0; j < 4; j++) {
                uint2 bv = wf[j * 32];
                bf[j][0] = bv.x; bf[j][1] = bv.y;
            }
            uint32_t af[2][4];
#pragma unroll
            for (int mt = 0; mt < 2; mt++) {
                uint32_t off = ((m0 + mt * 16 + rr) * LDA + kc * 16 + cbm) * 2;
                ldsm_x4(af[mt], abase + off);
            }
#pragma unroll
            for (int mt = 0; mt < 2; mt++) {
#pragma unroll
                for (int j = 0; j < 4; j++) {
                    mma16816h(acc[mt][j], af[mt], bf[j]);
                }
            }
        }
        __syncthreads();
    }

    // ---- epilogue ----
    {
        const int r0 = lane >> 2;
        const int c0 = (lane & 3) * 2;
#pragma unroll
        for (int mt = 0; mt < 2; mt++) {
#pragma unroll
            for (int j = 0; j < 4; j++) {
                const int row = wm * 32 + mt * 16 + r0;
                const int col = wn * 32 + j * 8 + c0;
                *reinterpret_cast<float2*>(s_out + row * LDO + col) =
                    make_float2(acc[mt][j][0], acc[mt][j][1]);
                *reinterpret_cast<float2*>(s_out + (row + 8) * LDO + col) =
                    make_float2(acc[mt][j][2], acc[mt][j][3]);
            }
        }
    }
    __syncthreads();

#pragma unroll 4
    for (int j = 0; j < 32; j++) {
        int i  = t + 256 * j;   // 8192 outputs
        int oc = i >> 6;
        int px = i & 63;
        out[(size_t)(b * C2 + oc) * HW + pix0 + px] =
            s_out[px * LDO + oc] + s_bias[oc];
    }
}

// ============================================================================
extern "C" void kernel_launch(void* const* d_in, const int* in_sizes, int n_in,
                              void* d_out, int out_size) {
    const float* x    = (const float*)d_in[0];
    const float* ow   = (const float*)d_in[1];
    const float* ob   = (const float*)d_in[2];
    const float* wgt  = (const float*)d_in[3];
    const float* bias = (const float*)d_in[4];
    float* out = (float*)d_out;

    dim3 gn(Hh, BATCH);
    nhwc_kernel<<<gn, 256>>>(x);

    prep_wfrag_kernel<<<(9 * 8 * 16 * 32 + 255) / 256, 256>>>(wgt);
    prep_ofrag_kernel<<<(9 * 8 * 3 * 32 + 255) / 256, 256>>>(ow);

    cudaFuncSetAttribute(offset_mma_kernel,
                         cudaFuncAttributeMaxDynamicSharedMemorySize,
                         OSMEM_TOTAL);
    dim3 g1(HW / 128, BATCH);
    offset_mma_kernel<<<g1, 256, OSMEM_TOTAL>>>(ob);

    cudaFuncSetAttribute(deform_mma_kernel,
                         cudaFuncAttributeMaxDynamicSharedMemorySize,
                         SMEM_TOTAL_D);
    dim3 g2(HW / MPX, BATCH);
    deform_mma_kernel<<<g2, 256, SMEM_TOTAL_D>>>(bias, out);
}

// round 10
// speedup vs baseline: 3.4621x; 1.0823x over previous
#include <cuda_runtime.h>
#include <cuda_fp16.h>
#include <cstdint>

// ---------------------------------------------------------------------------
// DSConv2d: offset conv (3x3, 128->18) + deformable conv (3x3, 128->128)
// B=16, C1=C2=128, H=W=80, fp32.
// Round 10: x pre-split to fp16 hi/lo NHWC planes; offset conv pipelined
// (double-buffered A, 1 sync/tap, N padded to 32); deform unchanged.
// ---------------------------------------------------------------------------

#define Hh 80
#define Ww 80
#define HW 6400
#define C1 128
#define C2 128
#define BATCH 16
#define OFFC 18

static __device__ float  g_offset[BATCH * OFFC * HW];   // 7.37 MB
static __device__ __half g_xTh[BATCH * HW * C1];        // 26.2 MB NHWC fp16 hi
static __device__ __half g_xTl[BATCH * HW * C1];        // 26.2 MB NHWC fp16 lo
static __device__ uint2  g_wF[9 * 8 * 16 * 32];         // deform B frags (fp16)
static __device__ uint4  g_oF[9 * 8 * 4 * 32];          // offset B frags (hi/lo), N=32

// ============================================================================
// common helpers
// ============================================================================
__device__ __forceinline__ uint32_t smem_u32(const void* p) {
    uint32_t a;
    asm("{ .reg .u64 t; cvta.to.shared.u64 t, %1; cvt.u32.u64 %0, t; }"
        : "=r"(a) : "l"(p));
    return a;
}

__device__ __forceinline__ void ldsm_x4(uint32_t* r, uint32_t saddr) {
    asm volatile("ldmatrix.sync.aligned.m8n8.x4.shared.b16 {%0,%1,%2,%3}, [%4];"
                 : "=r"(r[0]), "=r"(r[1]), "=r"(r[2]), "=r"(r[3])
                 : "r"(saddr));
}

__device__ __forceinline__ void mma16816h(float* d, const uint32_t* a,
                                          const uint32_t* b) {
    asm volatile(
        "mma.sync.aligned.m16n8k16.row.col.f32.f16.f16.f32 "
        "{%0,%1,%2,%3}, {%4,%5,%6,%7}, {%8,%9}, {%0,%1,%2,%3};"
        : "+f"(d[0]), "+f"(d[1]), "+f"(d[2]), "+f"(d[3])
        : "r"(a[0]), "r"(a[1]), "r"(a[2]), "r"(a[3]),
          "r"(b[0]), "r"(b[1]));
}

__device__ __forceinline__ uint32_t hsplit2(float va, float vb, uint32_t& lo) {
    __half ha = __float2half_rn(va);
    __half hb = __float2half_rn(vb);
    __half la = __float2half_rn(va - __half2float(ha));
    __half lb = __float2half_rn(vb - __half2float(hb));
    lo = ((uint32_t)__half_as_ushort(lb) << 16) | (uint32_t)__half_as_ushort(la);
    return ((uint32_t)__half_as_ushort(hb) << 16) | (uint32_t)__half_as_ushort(ha);
}

// ============================================================================
// Kernel 0a: NCHW -> NHWC fp16 hi/lo planes
// ============================================================================
__global__ __launch_bounds__(256) void nhwc_kernel(const float* __restrict__ x)
{
    __shared__ float tile[128][81];
    const int h = blockIdx.x;
    const int b = blockIdx.y;
    const int t = threadIdx.x;

    for (int idx = t; idx < 128 * 80; idx += 256) {
        int c = idx / 80;
        int w = idx - c * 80;
        tile[c][w] = x[((size_t)(b * C1 + c) * Hh + h) * Ww + w];
    }
    __syncthreads();
    for (int idx = t; idx < 80 * 128; idx += 256) {
        int w = idx >> 7;
        int c = idx & 127;
        float v = tile[c][w];
        __half hi = __float2half_rn(v);
        __half lo = __float2half_rn(v - __half2float(hi));
        size_t o = ((size_t)b * HW + h * Ww + w) * C1 + c;
        g_xTh[o] = hi;
        g_xTl[o] = lo;
    }
}

// ============================================================================
// Kernel 0b: deform weights -> m16n8k16 B frags, fp16 single-term
// ============================================================================
__global__ __launch_bounds__(256) void prep_wfrag_kernel(const float* __restrict__ wgt)
{
    int i = blockIdx.x * 256 + threadIdx.x;
    if (i >= 9 * 8 * 16 * 32) return;
    int lane = i & 31;
    int nf   = (i >> 5) & 15;
    int kc   = (i >> 9) & 7;
    int tap  = i >> 12;
    int n  = nf * 8 + (lane >> 2);
    int kb = kc * 16 + (lane & 3) * 2;

    __half h00 = __float2half_rn(wgt[(n * 128 + kb + 0) * 9 + tap]);
    __half h01 = __float2half_rn(wgt[(n * 128 + kb + 1) * 9 + tap]);
    __half h10 = __float2half_rn(wgt[(n * 128 + kb + 8) * 9 + tap]);
    __half h11 = __float2half_rn(wgt[(n * 128 + kb + 9) * 9 + tap]);

    uint2 v;
    v.x = ((uint32_t)__half_as_ushort(h01) << 16) | (uint32_t)__half_as_ushort(h00);
    v.y = ((uint32_t)__half_as_ushort(h11) << 16) | (uint32_t)__half_as_ushort(h10);
    g_wF[i] = v;
}

// ============================================================================
// Kernel 0c: offset weights -> B frags, fp16 hi/lo, N pad 18->32
// ============================================================================
__global__ __launch_bounds__(256) void prep_ofrag_kernel(const float* __restrict__ ow)
{
    int i = blockIdx.x * 256 + threadIdx.x;
    if (i >= 9 * 8 * 4 * 32) return;
    int lane = i & 31;
    int nf   = (i >> 5) & 3;
    int kc   = (i >> 7) & 7;
    int tap  = i >> 10;
    int n  = nf * 8 + (lane >> 2);
    int kb = kc * 16 + (lane & 3) * 2;

    float w00 = 0.f, w01 = 0.f, w10 = 0.f, w11 = 0.f;
    if (n < OFFC) {
        w00 = ow[(n * 128 + kb + 0) * 9 + tap];
        w01 = ow[(n * 128 + kb + 1) * 9 + tap];
        w10 = ow[(n * 128 + kb + 8) * 9 + tap];
        w11 = ow[(n * 128 + kb + 9) * 9 + tap];
    }
    uint4 v;
    uint32_t l01, l89;
    v.x = hsplit2(w00, w01, l01);
    v.y = hsplit2(w10, w11, l89);
    v.z = l01;
    v.w = l89;
    g_oF[i] = v;
}

// ============================================================================
// Kernel 1: offset conv, pipelined tensor-core implicit GEMM.
// Block = 64 px, N = 32 (18 real), K = 1152. 8 warps = 4 m-frags x 2 n-groups.
// A = fixed-window copies of pre-split hi/lo planes, double-buffered.
// 3-term MMA (ah*bh + ah*bl + al*bh). 1 sync/tap.
// ============================================================================
#define OM   64
#define OLDA 136
#define LDOF 33
#define OAB  (OM * OLDA * 2)                   // 17408 per matrix
#define OSM_OB   0
#define OSM_BUF0 1024
#define OBUFSZ   (2 * OAB)                     // Ah + Al = 34816
#define OSM_BUF1 (OSM_BUF0 + OBUFSZ)
#define OSMEM_TOTAL (OSM_BUF1 + OBUFSZ)        // 70656

__global__ __launch_bounds__(256, 3)
void offset_mma_kernel(const float* __restrict__ ob)
{
    extern __shared__ char smem[];
    const uint32_t sb = smem_u32(smem);
    float* s_ob  = reinterpret_cast<float*>(smem + OSM_OB);
    float* s_out = reinterpret_cast<float*>(smem + OSM_BUF0);  // reuse post-MMA

    const int t    = threadIdx.x;
    const int wid  = t >> 5;
    const int lane = t & 31;
    const int b    = blockIdx.y;
    const int pix0 = blockIdx.x * OM;
    const int wm   = wid & 3;    // m-frag: 16 px
    const int wn   = wid >> 2;   // n-group: 2 n-frags

    const __half* xh = g_xTh + (size_t)b * HW * C1;
    const __half* xl = g_xTl + (size_t)b * HW * C1;

    if (t < OFFC) s_ob[t] = ob[t];

    float acc[2][4];
#pragma unroll
    for (int j = 0; j < 2; j++)
#pragma unroll
        for (int r = 0; r < 4; r++) acc[j][r] = 0.f;

    // ldmatrix lane addressing
    const int tile = lane >> 3;
    const int rr   = ((tile & 1) << 3) + (lane & 7);
    const int cbm  = (tile >> 1) << 3;

    // A build: warp owns px = wid*8 .. wid*8+7 (copy hi/lo rows)
    auto build_into = [&](int bufsel, int tap) {
        __half* Ah = reinterpret_cast<__half*>(
            smem + (bufsel ? OSM_BUF1 : OSM_BUF0));
        __half* Al = reinterpret_cast<__half*>(
            smem + (bufsel ? OSM_BUF1 : OSM_BUF0) + OAB);
        const int ki = tap / 3;
        const int kj = tap % 3;
        const int pxbase = wid * 8;
#pragma unroll 2
        for (int i = 0; i < 8; i++) {
            const int px  = pxbase + i;
            const int pix = pix0 + px;
            const int ho  = pix / Ww;
            const int wo  = pix - ho * Ww;
            const int sy  = ho - 1 + ki;
            const int sx  = wo - 1 + kj;
            uint2 vh = make_uint2(0u, 0u), vl = make_uint2(0u, 0u);
            if (sy >= 0 && sy < Hh && sx >= 0 && sx < Ww) {
                const size_t ro = (size_t)(sy * Ww + sx) * C1;
                vh = *(reinterpret_cast<const uint2*>(xh + ro) + lane);
                vl = *(reinterpret_cast<const uint2*>(xl + ro) + lane);
            }
            *reinterpret_cast<uint2*>(Ah + px * OLDA + lane * 4) = vh;
            *reinterpret_cast<uint2*>(Al + px * OLDA + lane * 4) = vl;
        }
    };

    // ---- prologue ----
    build_into(0, 0);
    __syncthreads();

    // ---- pipelined main loop: 1 sync per tap ----
#pragma unroll 1
    for (int tap = 0; tap < 9; tap++) {
        const int cur = tap & 1;
        if (tap < 8) build_into(1 - cur, tap + 1);

        const uint32_t abase = sb + (cur ? OSM_BUF1 : OSM_BUF0);
        const int m0 = wm * 16;
#pragma unroll 1
        for (int kc = 0; kc < 8; kc++) {
            uint32_t bh[2][2], bl[2][2];
            const uint4* wf = g_oF + (((size_t)tap * 8 + kc) * 4 + wn * 2) * 32 + lane;
#pragma unroll
            for (int j = 0; j < 2; j++) {
                uint4 bv = wf[j * 32];
                bh[j][0] = bv.x; bh[j][1] = bv.y;
                bl[j][0] = bv.z; bl[j][1] = bv.w;
            }
            uint32_t ah[4], al[4];
            uint32_t off = ((m0 + rr) * OLDA + kc * 16 + cbm) * 2;
            ldsm_x4(ah, abase + off);
            ldsm_x4(al, abase + OAB + off);
#pragma unroll
            for (int j = 0; j < 2; j++) {
                mma16816h(acc[j], ah, bh[j]);
                mma16816h(acc[j], ah, bl[j]);
                mma16816h(acc[j], al, bh[j]);
            }
        }
        __syncthreads();
    }

    // ---- epilogue: acc -> s_out[px][33] -> g_offset (18 real channels) ----
    {
        const int r0 = lane >> 2;
        const int c0 = (lane & 3) * 2;
        const int m0 = wm * 16;
#pragma unroll
        for (int j = 0; j < 2; j++) {
            const int col = wn * 16 + j * 8 + c0;
            if (col < OFFC) {
                s_out[(m0 + r0) * LDOF + col]     = acc[j][0];
                s_out[(m0 + r0 + 8) * LDOF + col] = acc[j][2];
            }
            if (col + 1 < OFFC) {
                s_out[(m0 + r0) * LDOF + col + 1]     = acc[j][1];
                s_out[(m0 + r0 + 8) * LDOF + col + 1] = acc[j][3];
            }
        }
    }
    __syncthreads();

#pragma unroll
    for (int j = 0; j < 5; j++) {
        int i = t + 256 * j;   // 1152 outputs = 18ch x 64px
        if (i < OFFC * OM) {
            int ch = i >> 6;
            int px = i & 63;
            g_offset[(size_t)(b * OFFC + ch) * HW + pix0 + px] =
                s_out[px * LDOF + ch] + s_ob[ch];
        }
    }
}

// ============================================================================
// Kernel 2: deformable conv. 64px x 128oc, 3 CTAs/SM, software-pipelined.
// fp16 NHWC gather (LDG.64 rows), single fp16 A, frag-packed fp16 B.
// (unchanged from round 9 — validated at 165us / rel_err model)
// ============================================================================
#define MPX 64
#define LDA 136
#define LDO 132

#define SMO_BIAS 0
#define SMO_BUF0 1024
#define ABYTES   (MPX * LDA * 2)
#define SMO_BUF1 (SMO_BUF0 + ABYTES)
#define SMEM_TOTAL_D (SMO_BUF1 + ABYTES)  // 35840

__global__ __launch_bounds__(256, 3)
void deform_mma_kernel(const float* __restrict__ bias,
                       float* __restrict__ out)
{
    extern __shared__ char smem[];
    const uint32_t sb = smem_u32(smem);
    float* s_bias = reinterpret_cast<float*>(smem + SMO_BIAS);
    float* s_out  = reinterpret_cast<float*>(smem + SMO_BUF0);

    const int t    = threadIdx.x;
    const int wid  = t >> 5;
    const int lane = t & 31;
    const int b    = blockIdx.y;
    const int pix0 = blockIdx.x * MPX;
    const int wm   = wid & 1;
    const int wn   = wid >> 1;

    const __half* xTb = g_xTh + (size_t)b * HW * C1;

    float acc[2][4][4];
#pragma unroll
    for (int mt = 0; mt < 2; mt++)
#pragma unroll
        for (int j = 0; j < 4; j++)
#pragma unroll
            for (int r = 0; r < 4; r++) acc[mt][j][r] = 0.f;

    if (t < 128) s_bias[t] = bias[t];

    const int tile = lane >> 3;
    const int rr   = ((tile & 1) << 3) + (lane & 7);
    const int cbm  = (tile >> 1) << 3;

    const int l8     = lane & 7;
    const int pxm    = pix0 + wid * 8 + l8;
    const int hom    = pxm / Ww;
    const int wom    = pxm - hom * Ww;
    float m_w0, m_w1, m_w2, m_w3;
    int   m_o0, m_o1, m_o2, m_o3;

    auto compute_meta = [&](int tap) {
        const int ki = tap / 3;
        const int kj = tap % 3;
        float dy = g_offset[(b * OFFC + 2 * tap) * HW + pxm];
        float dx = g_offset[(b * OFFC + 2 * tap + 1) * HW + pxm];
        float py  = (float)(hom - 1 + ki) + dy;
        float pxx = (float)(wom - 1 + kj) + dx;
        float y0 = floorf(py);
        float x0 = floorf(pxx);
        float wy1 = py - y0, wy0 = 1.f - wy1;
        float wx1 = pxx - x0, wx0 = 1.f - wx1;

        float yc0 = y0, yc1 = y0 + 1.f, xc0 = x0, xc1 = x0 + 1.f;
        bool vy0 = (yc0 >= 0.f) && (yc0 < (float)Hh);
        bool vy1 = (yc1 >= 0.f) && (yc1 < (float)Hh);
        bool vx0 = (xc0 >= 0.f) && (xc0 < (float)Ww);
        bool vx1 = (xc1 >= 0.f) && (xc1 < (float)Ww);
        int iy0 = (int)fminf(fmaxf(yc0, 0.f), (float)(Hh - 1));
        int iy1 = (int)fminf(fmaxf(yc1, 0.f), (float)(Hh - 1));
        int ix0 = (int)fminf(fmaxf(xc0, 0.f), (float)(Ww - 1));
        int ix1 = (int)fminf(fmaxf(xc1, 0.f), (float)(Ww - 1));
        m_w0 = (vy0 && vx0) ? wy0 * wx0 : 0.f;  m_o0 = iy0 * Ww + ix0;
        m_w1 = (vy0 && vx1) ? wy0 * wx1 : 0.f;  m_o1 = iy0 * Ww + ix1;
        m_w2 = (vy1 && vx0) ? wy1 * wx0 : 0.f;  m_o2 = iy1 * Ww + ix0;
        m_w3 = (vy1 && vx1) ? wy1 * wx1 : 0.f;  m_o3 = iy1 * Ww + ix1;
    };

    auto gather_into = [&](int bufsel) {
        __half* Ah = reinterpret_cast<__half*>(
            smem + (bufsel ? SMO_BUF1 : SMO_BUF0));
        const int pxbase = wid * 8;
#pragma unroll 2
        for (int i = 0; i < 8; i++) {
            const int px = pxbase + i;
            const float w0 = __shfl_sync(0xffffffffu, m_w0, i);
            const float w1 = __shfl_sync(0xffffffffu, m_w1, i);
            const float w2 = __shfl_sync(0xffffffffu, m_w2, i);
            const float w3 = __shfl_sync(0xffffffffu, m_w3, i);
            const int o0 = __shfl_sync(0xffffffffu, m_o0, i);
            const int o1 = __shfl_sync(0xffffffffu, m_o1, i);
            const int o2 = __shfl_sync(0xffffffffu, m_o2, i);
            const int o3 = __shfl_sync(0xffffffffu, m_o3, i);
            uint2 r0 = *(reinterpret_cast<const uint2*>(xTb + (size_t)o0 * C1) + lane);
            uint2 r1 = *(reinterpret_cast<const uint2*>(xTb + (size_t)o1 * C1) + lane);
            uint2 r2 = *(reinterpret_cast<const uint2*>(xTb + (size_t)o2 * C1) + lane);
            uint2 r3 = *(reinterpret_cast<const uint2*>(xTb + (size_t)o3 * C1) + lane);
            float2 v0a = __half22float2(*reinterpret_cast<__half2*>(&r0.x));
            float2 v0b = __half22float2(*reinterpret_cast<__half2*>(&r0.y));
            float2 v1a = __half22float2(*reinterpret_cast<__half2*>(&r1.x));
            float2 v1b = __half22float2(*reinterpret_cast<__half2*>(&r1.y));
            float2 v2a = __half22float2(*reinterpret_cast<__half2*>(&r2.x));
            float2 v2b = __half22float2(*reinterpret_cast<__half2*>(&r2.y));
            float2 v3a = __half22float2(*reinterpret_cast<__half2*>(&r3.x));
            float2 v3b = __half22float2(*reinterpret_cast<__half2*>(&r3.y));
            float a0 = w0 * v0a.x; a0 = fmaf(w1, v1a.x, a0);
            a0 = fmaf(w2, v2a.x, a0); a0 = fmaf(w3, v3a.x, a0);
            float a1 = w0 * v0a.y; a1 = fmaf(w1, v1a.y, a1);
            a1 = fmaf(w2, v2a.y, a1); a1 = fmaf(w3, v3a.y, a1);
            float a2 = w0 * v0b.x; a2 = fmaf(w1, v1b.x, a2);
            a2 = fmaf(w2, v2b.x, a2); a2 = fmaf(w3, v3b.x, a2);
            float a3 = w0 * v0b.y; a3 = fmaf(w1, v1b.y, a3);
            a3 = fmaf(w2, v2b.y, a3); a3 = fmaf(w3, v3b.y, a3);
            __half2 h01 = __floats2half2_rn(a0, a1);
            __half2 h23 = __floats2half2_rn(a2, a3);
            uint2 pk;
            pk.x = *reinterpret_cast<uint32_t*>(&h01);
            pk.y = *reinterpret_cast<uint32_t*>(&h23);
            *reinterpret_cast<uint2*>(Ah + px * LDA + lane * 4) = pk;
        }
    };

    compute_meta(0);
    gather_into(0);
    __syncthreads();

#pragma unroll 1
    for (int tap = 0; tap < 9; tap++) {
        const int cur = tap & 1;
        if (tap < 8) {
            compute_meta(tap + 1);
            gather_into(1 - cur);
        }

        const uint32_t abase = sb + (cur ? SMO_BUF1 : SMO_BUF0);
        const int m0 = wm * 32;
#pragma unroll 1
        for (int kc = 0; kc < 8; kc++) {
            uint32_t bf[4][2];
            const uint2* wf = g_wF + (((size_t)tap * 8 + kc) * 16 + wn * 4) * 32 + lane;
#pragma unroll
            for (int j = 0; j < 4; j++) {
                uint2 bv = wf[j * 32];
                bf[j][0] = bv.x; bf[j][1] = bv.y;
            }
            uint32_t af[2][4];
#pragma unroll
            for (int mt = 0; mt < 2; mt++) {
                uint32_t off = ((m0 + mt * 16 + rr) * LDA + kc * 16 + cbm) * 2;
                ldsm_x4(af[mt], abase + off);
            }
#pragma unroll
            for (int mt = 0; mt < 2; mt++) {
#pragma unroll
                for (int j = 0; j < 4; j++) {
                    mma16816h(acc[mt][j], af[mt], bf[j]);
                }
            }
        }
        __syncthreads();
    }

    {
        const int r0 = lane >> 2;
        const int c0 = (lane & 3) * 2;
#pragma unroll
        for (int mt = 0; mt < 2; mt++) {
#pragma unroll
            for (int j = 0; j < 4; j++) {
                const int row = wm * 32 + mt * 16 + r0;
                const int col = wn * 32 + j * 8 + c0;
                *reinterpret_cast<float2*>(s_out + row * LDO + col) =
                    make_float2(acc[mt][j][0], acc[mt][j][1]);
                *reinterpret_cast<float2*>(s_out + (row + 8) * LDO + col) =
                    make_float2(acc[mt][j][2], acc[mt][j][3]);
            }
        }
    }
    __syncthreads();

#pragma unroll 4
    for (int j = 0; j < 32; j++) {
        int i  = t + 256 * j;
        int oc = i >> 6;
        int px = i & 63;
        out[(size_t)(b * C2 + oc) * HW + pix0 + px] =
            s_out[px * LDO + oc] + s_bias[oc];
    }
}

// ============================================================================
extern "C" void kernel_launch(void* const* d_in, const int* in_sizes, int n_in,
                              void* d_out, int out_size) {
    const float* x    = (const float*)d_in[0];
    const float* ow   = (const float*)d_in[1];
    const float* ob   = (const float*)d_in[2];
    const float* wgt  = (const float*)d_in[3];
    const float* bias = (const float*)d_in[4];
    float* out = (float*)d_out;

    dim3 gn(Hh, BATCH);
    nhwc_kernel<<<gn, 256>>>(x);

    prep_wfrag_kernel<<<(9 * 8 * 16 * 32 + 255) / 256, 256>>>(wgt);
    prep_ofrag_kernel<<<(9 * 8 * 4 * 32 + 255) / 256, 256>>>(ow);

    cudaFuncSetAttribute(offset_mma_kernel,
                         cudaFuncAttributeMaxDynamicSharedMemorySize,
                         OSMEM_TOTAL);
    dim3 g1(HW / OM, BATCH);
    offset_mma_kernel<<<g1, 256, OSMEM_TOTAL>>>(ob);

    cudaFuncSetAttribute(deform_mma_kernel,
                         cudaFuncAttributeMaxDynamicSharedMemorySize,
                         SMEM_TOTAL_D);
    dim3 g2(HW / MPX, BATCH);
    deform_mma_kernel<<<g2, 256, SMEM_TOTAL_D>>>(bias, out);
}

// round 11
// speedup vs baseline: 3.5989x; 1.0395x over previous
#include <cuda_runtime.h>
#include <cuda_fp16.h>
#include <cstdint>

// ---------------------------------------------------------------------------
// DSConv2d: offset conv (3x3, 128->18) + deformable conv (3x3, 128->128)
// B=16, C1=C2=128, H=W=80, fp32.
// Round 11: batch-split two-stream overlap of offset & deform phases
// (kernels identical to round 10 + b0 grid offset).
// ---------------------------------------------------------------------------

#define Hh 80
#define Ww 80
#define HW 6400
#define C1 128
#define C2 128
#define BATCH 16
#define OFFC 18

static __device__ float  g_offset[BATCH * OFFC * HW];   // 7.37 MB
static __device__ __half g_xTh[BATCH * HW * C1];        // 26.2 MB NHWC fp16 hi
static __device__ __half g_xTl[BATCH * HW * C1];        // 26.2 MB NHWC fp16 lo
static __device__ uint2  g_wF[9 * 8 * 16 * 32];         // deform B frags (fp16)
static __device__ uint4  g_oF[9 * 8 * 4 * 32];          // offset B frags (hi/lo), N=32

// ============================================================================
// common helpers
// ============================================================================
__device__ __forceinline__ uint32_t smem_u32(const void* p) {
    uint32_t a;
    asm("{ .reg .u64 t; cvta.to.shared.u64 t, %1; cvt.u32.u64 %0, t; }"
        : "=r"(a) : "l"(p));
    return a;
}

__device__ __forceinline__ void ldsm_x4(uint32_t* r, uint32_t saddr) {
    asm volatile("ldmatrix.sync.aligned.m8n8.x4.shared.b16 {%0,%1,%2,%3}, [%4];"
                 : "=r"(r[0]), "=r"(r[1]), "=r"(r[2]), "=r"(r[3])
                 : "r"(saddr));
}

__device__ __forceinline__ void mma16816h(float* d, const uint32_t* a,
                                          const uint32_t* b) {
    asm volatile(
        "mma.sync.aligned.m16n8k16.row.col.f32.f16.f16.f32 "
        "{%0,%1,%2,%3}, {%4,%5,%6,%7}, {%8,%9}, {%0,%1,%2,%3};"
        : "+f"(d[0]), "+f"(d[1]), "+f"(d[2]), "+f"(d[3])
        : "r"(a[0]), "r"(a[1]), "r"(a[2]), "r"(a[3]),
          "r"(b[0]), "r"(b[1]));
}

__device__ __forceinline__ uint32_t hsplit2(float va, float vb, uint32_t& lo) {
    __half ha = __float2half_rn(va);
    __half hb = __float2half_rn(vb);
    __half la = __float2half_rn(va - __half2float(ha));
    __half lb = __float2half_rn(vb - __half2float(hb));
    lo = ((uint32_t)__half_as_ushort(lb) << 16) | (uint32_t)__half_as_ushort(la);
    return ((uint32_t)__half_as_ushort(hb) << 16) | (uint32_t)__half_as_ushort(ha);
}

// ============================================================================
// Kernel 0a: NCHW -> NHWC fp16 hi/lo planes
// ============================================================================
__global__ __launch_bounds__(256) void nhwc_kernel(const float* __restrict__ x)
{
    __shared__ float tile[128][81];
    const int h = blockIdx.x;
    const int b = blockIdx.y;
    const int t = threadIdx.x;

    for (int idx = t; idx < 128 * 80; idx += 256) {
        int c = idx / 80;
        int w = idx - c * 80;
        tile[c][w] = x[((size_t)(b * C1 + c) * Hh + h) * Ww + w];
    }
    __syncthreads();
    for (int idx = t; idx < 80 * 128; idx += 256) {
        int w = idx >> 7;
        int c = idx & 127;
        float v = tile[c][w];
        __half hi = __float2half_rn(v);
        __half lo = __float2half_rn(v - __half2float(hi));
        size_t o = ((size_t)b * HW + h * Ww + w) * C1 + c;
        g_xTh[o] = hi;
        g_xTl[o] = lo;
    }
}

// ============================================================================
// Kernel 0b: deform weights -> m16n8k16 B frags, fp16 single-term
// ============================================================================
__global__ __launch_bounds__(256) void prep_wfrag_kernel(const float* __restrict__ wgt)
{
    int i = blockIdx.x * 256 + threadIdx.x;
    if (i >= 9 * 8 * 16 * 32) return;
    int lane = i & 31;
    int nf   = (i >> 5) & 15;
    int kc   = (i >> 9) & 7;
    int tap  = i >> 12;
    int n  = nf * 8 + (lane >> 2);
    int kb = kc * 16 + (lane & 3) * 2;

    __half h00 = __float2half_rn(wgt[(n * 128 + kb + 0) * 9 + tap]);
    __half h01 = __float2half_rn(wgt[(n * 128 + kb + 1) * 9 + tap]);
    __half h10 = __float2half_rn(wgt[(n * 128 + kb + 8) * 9 + tap]);
    __half h11 = __float2half_rn(wgt[(n * 128 + kb + 9) * 9 + tap]);

    uint2 v;
    v.x = ((uint32_t)__half_as_ushort(h01) << 16) | (uint32_t)__half_as_ushort(h00);
    v.y = ((uint32_t)__half_as_ushort(h11) << 16) | (uint32_t)__half_as_ushort(h10);
    g_wF[i] = v;
}

// ============================================================================
// Kernel 0c: offset weights -> B frags, fp16 hi/lo, N pad 18->32
// ============================================================================
__global__ __launch_bounds__(256) void prep_ofrag_kernel(const float* __restrict__ ow)
{
    int i = blockIdx.x * 256 + threadIdx.x;
    if (i >= 9 * 8 * 4 * 32) return;
    int lane = i & 31;
    int nf   = (i >> 5) & 3;
    int kc   = (i >> 7) & 7;
    int tap  = i >> 10;
    int n  = nf * 8 + (lane >> 2);
    int kb = kc * 16 + (lane & 3) * 2;

    float w00 = 0.f, w01 = 0.f, w10 = 0.f, w11 = 0.f;
    if (n < OFFC) {
        w00 = ow[(n * 128 + kb + 0) * 9 + tap];
        w01 = ow[(n * 128 + kb + 1) * 9 + tap];
        w10 = ow[(n * 128 + kb + 8) * 9 + tap];
        w11 = ow[(n * 128 + kb + 9) * 9 + tap];
    }
    uint4 v;
    uint32_t l01, l89;
    v.x = hsplit2(w00, w01, l01);
    v.y = hsplit2(w10, w11, l89);
    v.z = l01;
    v.w = l89;
    g_oF[i] = v;
}

// ============================================================================
// Kernel 1: offset conv, pipelined tensor-core implicit GEMM (round 10).
// ============================================================================
#define OM   64
#define OLDA 136
#define LDOF 33
#define OAB  (OM * OLDA * 2)
#define OSM_OB   0
#define OSM_BUF0 1024
#define OBUFSZ   (2 * OAB)
#define OSM_BUF1 (OSM_BUF0 + OBUFSZ)
#define OSMEM_TOTAL (OSM_BUF1 + OBUFSZ)        // 70656

__global__ __launch_bounds__(256, 3)
void offset_mma_kernel(const float* __restrict__ ob, int b0)
{
    extern __shared__ char smem[];
    float* s_ob  = reinterpret_cast<float*>(smem + OSM_OB);
    float* s_out = reinterpret_cast<float*>(smem + OSM_BUF0);

    const int t    = threadIdx.x;
    const int wid  = t >> 5;
    const int lane = t & 31;
    const int b    = blockIdx.y + b0;
    const int pix0 = blockIdx.x * OM;
    const int wm   = wid & 3;
    const int wn   = wid >> 2;

    const __half* xh = g_xTh + (size_t)b * HW * C1;
    const __half* xl = g_xTl + (size_t)b * HW * C1;

    if (t < OFFC) s_ob[t] = ob[t];

    float acc[2][4];
#pragma unroll
    for (int j = 0; j < 2; j++)
#pragma unroll
        for (int r = 0; r < 4; r++) acc[j][r] = 0.f;

    const int tile = lane >> 3;
    const int rr   = ((tile & 1) << 3) + (lane & 7);
    const int cbm  = (tile >> 1) << 3;

    auto build_into = [&](int bufsel, int tap) {
        __half* Ah = reinterpret_cast<__half*>(
            smem + (bufsel ? OSM_BUF1 : OSM_BUF0));
        __half* Al = reinterpret_cast<__half*>(
            smem + (bufsel ? OSM_BUF1 : OSM_BUF0) + OAB);
        const int ki = tap / 3;
        const int kj = tap % 3;
        const int pxbase = wid * 8;
#pragma unroll 2
        for (int i = 0; i < 8; i++) {
            const int px  = pxbase + i;
            const int pix = pix0 + px;
            const int ho  = pix / Ww;
            const int wo  = pix - ho * Ww;
            const int sy  = ho - 1 + ki;
            const int sx  = wo - 1 + kj;
            uint2 vh = make_uint2(0u, 0u), vl = make_uint2(0u, 0u);
            if (sy >= 0 && sy < Hh && sx >= 0 && sx < Ww) {
                const size_t ro = (size_t)(sy * Ww + sx) * C1;
                vh = *(reinterpret_cast<const uint2*>(xh + ro) + lane);
                vl = *(reinterpret_cast<const uint2*>(xl + ro) + lane);
            }
            *reinterpret_cast<uint2*>(Ah + px * OLDA + lane * 4) = vh;
            *reinterpret_cast<uint2*>(Al + px * OLDA + lane * 4) = vl;
        }
    };

    build_into(0, 0);
    __syncthreads();

    const uint32_t sb = smem_u32(smem);
#pragma unroll 1
    for (int tap = 0; tap < 9; tap++) {
        const int cur = tap & 1;
        if (tap < 8) build_into(1 - cur, tap + 1);

        const uint32_t abase = sb + (cur ? OSM_BUF1 : OSM_BUF0);
        const int m0 = wm * 16;
#pragma unroll 1
        for (int kc = 0; kc < 8; kc++) {
            uint32_t bh[2][2], bl[2][2];
            const uint4* wf = g_oF + (((size_t)tap * 8 + kc) * 4 + wn * 2) * 32 + lane;
#pragma unroll
            for (int j = 0; j < 2; j++) {
                uint4 bv = wf[j * 32];
                bh[j][0] = bv.x; bh[j][1] = bv.y;
                bl[j][0] = bv.z; bl[j][1] = bv.w;
            }
            uint32_t ah[4], al[4];
            uint32_t off = ((m0 + rr) * OLDA + kc * 16 + cbm) * 2;
            ldsm_x4(ah, abase + off);
            ldsm_x4(al, abase + OAB + off);
#pragma unroll
            for (int j = 0; j < 2; j++) {
                mma16816h(acc[j], ah, bh[j]);
                mma16816h(acc[j], ah, bl[j]);
                mma16816h(acc[j], al, bh[j]);
            }
        }
        __syncthreads();
    }

    {
        const int r0 = lane >> 2;
        const int c0 = (lane & 3) * 2;
        const int m0 = wm * 16;
#pragma unroll
        for (int j = 0; j < 2; j++) {
            const int col = wn * 16 + j * 8 + c0;
            if (col < OFFC) {
                s_out[(m0 + r0) * LDOF + col]     = acc[j][0];
                s_out[(m0 + r0 + 8) * LDOF + col] = acc[j][2];
            }
            if (col + 1 < OFFC) {
                s_out[(m0 + r0) * LDOF + col + 1]     = acc[j][1];
                s_out[(m0 + r0 + 8) * LDOF + col + 1] = acc[j][3];
            }
        }
    }
    __syncthreads();

#pragma unroll
    for (int j = 0; j < 5; j++) {
        int i = t + 256 * j;
        if (i < OFFC * OM) {
            int ch = i >> 6;
            int px = i & 63;
            g_offset[(size_t)(b * OFFC + ch) * HW + pix0 + px] =
                s_out[px * LDOF + ch] + s_ob[ch];
        }
    }
}

// ============================================================================
// Kernel 2: deformable conv (round 9/10, validated) + b0 offset.
// ============================================================================
#define MPX 64
#define LDA 136
#define LDO 132

#define SMO_BIAS 0
#define SMO_BUF0 1024
#define ABYTES   (MPX * LDA * 2)
#define SMO_BUF1 (SMO_BUF0 + ABYTES)
#define SMEM_TOTAL_D (SMO_BUF1 + ABYTES)  // 35840

__global__ __launch_bounds__(256, 3)
void deform_mma_kernel(const float* __restrict__ bias,
                       float* __restrict__ out, int b0)
{
    extern __shared__ char smem[];
    const uint32_t sb = smem_u32(smem);
    float* s_bias = reinterpret_cast<float*>(smem + SMO_BIAS);
    float* s_out  = reinterpret_cast<float*>(smem + SMO_BUF0);

    const int t    = threadIdx.x;
    const int wid  = t >> 5;
    const int lane = t & 31;
    const int b    = blockIdx.y + b0;
    const int pix0 = blockIdx.x * MPX;
    const int wm   = wid & 1;
    const int wn   = wid >> 1;

    const __half* xTb = g_xTh + (size_t)b * HW * C1;

    float acc[2][4][4];
#pragma unroll
    for (int mt = 0; mt < 2; mt++)
#pragma unroll
        for (int j = 0; j < 4; j++)
#pragma unroll
            for (int r = 0; r < 4; r++) acc[mt][j][r] = 0.f;

    if (t < 128) s_bias[t] = bias[t];

    const int tile = lane >> 3;
    const int rr   = ((tile & 1) << 3) + (lane & 7);
    const int cbm  = (tile >> 1) << 3;

    const int l8     = lane & 7;
    const int pxm    = pix0 + wid * 8 + l8;
    const int hom    = pxm / Ww;
    const int wom    = pxm - hom * Ww;
    float m_w0, m_w1, m_w2, m_w3;
    int   m_o0, m_o1, m_o2, m_o3;

    auto compute_meta = [&](int tap) {
        const int ki = tap / 3;
        const int kj = tap % 3;
        float dy = g_offset[(b * OFFC + 2 * tap) * HW + pxm];
        float dx = g_offset[(b * OFFC + 2 * tap + 1) * HW + pxm];
        float py  = (float)(hom - 1 + ki) + dy;
        float pxx = (float)(wom - 1 + kj) + dx;
        float y0 = floorf(py);
        float x0 = floorf(pxx);
        float wy1 = py - y0, wy0 = 1.f - wy1;
        float wx1 = pxx - x0, wx0 = 1.f - wx1;

        float yc0 = y0, yc1 = y0 + 1.f, xc0 = x0, xc1 = x0 + 1.f;
        bool vy0 = (yc0 >= 0.f) && (yc0 < (float)Hh);
        bool vy1 = (yc1 >= 0.f) && (yc1 < (float)Hh);
        bool vx0 = (xc0 >= 0.f) && (xc0 < (float)Ww);
        bool vx1 = (xc1 >= 0.f) && (xc1 < (float)Ww);
        int iy0 = (int)fminf(fmaxf(yc0, 0.f), (float)(Hh - 1));
        int iy1 = (int)fminf(fmaxf(yc1, 0.f), (float)(Hh - 1));
        int ix0 = (int)fminf(fmaxf(xc0, 0.f), (float)(Ww - 1));
        int ix1 = (int)fminf(fmaxf(xc1, 0.f), (float)(Ww - 1));
        m_w0 = (vy0 && vx0) ? wy0 * wx0 : 0.f;  m_o0 = iy0 * Ww + ix0;
        m_w1 = (vy0 && vx1) ? wy0 * wx1 : 0.f;  m_o1 = iy0 * Ww + ix1;
        m_w2 = (vy1 && vx0) ? wy1 * wx0 : 0.f;  m_o2 = iy1 * Ww + ix0;
        m_w3 = (vy1 && vx1) ? wy1 * wx1 : 0.f;  m_o3 = iy1 * Ww + ix1;
    };

    auto gather_into = [&](int bufsel) {
        __half* Ah = reinterpret_cast<__half*>(
            smem + (bufsel ? SMO_BUF1 : SMO_BUF0));
        const int pxbase = wid * 8;
#pragma unroll 2
        for (int i = 0; i < 8; i++) {
            const int px = pxbase + i;
            const float w0 = __shfl_sync(0xffffffffu, m_w0, i);
            const float w1 = __shfl_sync(0xffffffffu, m_w1, i);
            const float w2 = __shfl_sync(0xffffffffu, m_w2, i);
            const float w3 = __shfl_sync(0xffffffffu, m_w3, i);
            const int o0 = __shfl_sync(0xffffffffu, m_o0, i);
            const int o1 = __shfl_sync(0xffffffffu, m_o1, i);
            const int o2 = __shfl_sync(0xffffffffu, m_o2, i);
            const int o3 = __shfl_sync(0xffffffffu, m_o3, i);
            uint2 r0 = *(reinterpret_cast<const uint2*>(xTb + (size_t)o0 * C1) + lane);
            uint2 r1 = *(reinterpret_cast<const uint2*>(xTb + (size_t)o1 * C1) + lane);
            uint2 r2 = *(reinterpret_cast<const uint2*>(xTb + (size_t)o2 * C1) + lane);
            uint2 r3 = *(reinterpret_cast<const uint2*>(xTb + (size_t)o3 * C1) + lane);
            float2 v0a = __half22float2(*reinterpret_cast<__half2*>(&r0.x));
            float2 v0b = __half22float2(*reinterpret_cast<__half2*>(&r0.y));
            float2 v1a = __half22float2(*reinterpret_cast<__half2*>(&r1.x));
            float2 v1b = __half22float2(*reinterpret_cast<__half2*>(&r1.y));
            float2 v2a = __half22float2(*reinterpret_cast<__half2*>(&r2.x));
            float2 v2b = __half22float2(*reinterpret_cast<__half2*>(&r2.y));
            float2 v3a = __half22float2(*reinterpret_cast<__half2*>(&r3.x));
            float2 v3b = __half22float2(*reinterpret_cast<__half2*>(&r3.y));
            float a0 = w0 * v0a.x; a0 = fmaf(w1, v1a.x, a0);
            a0 = fmaf(w2, v2a.x, a0); a0 = fmaf(w3, v3a.x, a0);
            float a1 = w0 * v0a.y; a1 = fmaf(w1, v1a.y, a1);
            a1 = fmaf(w2, v2a.y, a1); a1 = fmaf(w3, v3a.y, a1);
            float a2 = w0 * v0b.x; a2 = fmaf(w1, v1b.x, a2);
            a2 = fmaf(w2, v2b.x, a2); a2 = fmaf(w3, v3b.x, a2);
            float a3 = w0 * v0b.y; a3 = fmaf(w1, v1b.y, a3);
            a3 = fmaf(w2, v2b.y, a3); a3 = fmaf(w3, v3b.y, a3);
            __half2 h01 = __floats2half2_rn(a0, a1);
            __half2 h23 = __floats2half2_rn(a2, a3);
            uint2 pk;
            pk.x = *reinterpret_cast<uint32_t*>(&h01);
            pk.y = *reinterpret_cast<uint32_t*>(&h23);
            *reinterpret_cast<uint2*>(Ah + px * LDA + lane * 4) = pk;
        }
    };

    compute_meta(0);
    gather_into(0);
    __syncthreads();

#pragma unroll 1
    for (int tap = 0; tap < 9; tap++) {
        const int cur = tap & 1;
        if (tap < 8) {
            compute_meta(tap + 1);
            gather_into(1 - cur);
        }

        const uint32_t abase = sb + (cur ? SMO_BUF1 : SMO_BUF0);
        const int m0 = wm * 32;
#pragma unroll 1
        for (int kc = 0; kc < 8; kc++) {
            uint32_t bf[4][2];
            const uint2* wf = g_wF + (((size_t)tap * 8 + kc) * 16 + wn * 4) * 32 + lane;
#pragma unroll
            for (int j = 0; j < 4; j++) {
                uint2 bv = wf[j * 32];
                bf[j][0] = bv.x; bf[j][1] = bv.y;
            }
            uint32_t af[2][4];
#pragma unroll
            for (int mt = 0; mt < 2; mt++) {
                uint32_t off = ((m0 + mt * 16 + rr) * LDA + kc * 16 + cbm) * 2;
                ldsm_x4(af[mt], abase + off);
            }
#pragma unroll
            for (int mt = 0; mt < 2; mt++) {
#pragma unroll
                for (int j = 0; j < 4; j++) {
                    mma16816h(acc[mt][j], af[mt], bf[j]);
                }
            }
        }
        __syncthreads();
    }

    {
        const int r0 = lane >> 2;
        const int c0 = (lane & 3) * 2;
#pragma unroll
        for (int mt = 0; mt < 2; mt++) {
#pragma unroll
            for (int j = 0; j < 4; j++) {
                const int row = wm * 32 + mt * 16 + r0;
                const int col = wn * 32 + j * 8 + c0;
                *reinterpret_cast<float2*>(s_out + row * LDO + col) =
                    make_float2(acc[mt][j][0], acc[mt][j][1]);
                *reinterpret_cast<float2*>(s_out + (row + 8) * LDO + col) =
                    make_float2(acc[mt][j][2], acc[mt][j][3]);
            }
        }
    }
    __syncthreads();

#pragma unroll 4
    for (int j = 0; j < 32; j++) {
        int i  = t + 256 * j;
        int oc = i >> 6;
        int px = i & 63;
        out[(size_t)(b * C2 + oc) * HW + pix0 + px] =
            s_out[px * LDO + oc] + s_bias[oc];
    }
}

// ============================================================================
// Launch: batch-split across two streams; second stream forked from the
// capture/default stream via events (multi-stream capture pattern).
// Streams/events are host-side objects (no device memory) and are
// intentionally not destroyed (kernel_launch host code runs only a few
// times; destroying a stream with captured work before EndCapture is
// illegal).
// ============================================================================
#define BHALF (BATCH / 2)

extern "C" void kernel_launch(void* const* d_in, const int* in_sizes, int n_in,
                              void* d_out, int out_size) {
    const float* x    = (const float*)d_in[0];
    const float* ow   = (const float*)d_in[1];
    const float* ob   = (const float*)d_in[2];
    const float* wgt  = (const float*)d_in[3];
    const float* bias = (const float*)d_in[4];
    float* out = (float*)d_out;

    cudaStream_t s1;
    cudaStreamCreateWithFlags(&s1, cudaStreamNonBlocking);
    cudaEvent_t eFork, eJoin;
    cudaEventCreateWithFlags(&eFork, cudaEventDisableTiming);
    cudaEventCreateWithFlags(&eJoin, cudaEventDisableTiming);

    // ---- shared prep on default stream ----
    dim3 gn(Hh, BATCH);
    nhwc_kernel<<<gn, 256>>>(x);
    prep_wfrag_kernel<<<(9 * 8 * 16 * 32 + 255) / 256, 256>>>(wgt);
    prep_ofrag_kernel<<<(9 * 8 * 4 * 32 + 255) / 256, 256>>>(ow);

    cudaFuncSetAttribute(offset_mma_kernel,
                         cudaFuncAttributeMaxDynamicSharedMemorySize,
                         OSMEM_TOTAL);
    cudaFuncSetAttribute(deform_mma_kernel,
                         cudaFuncAttributeMaxDynamicSharedMemorySize,
                         SMEM_TOTAL_D);

    // ---- fork: s1 waits until preps complete ----
    cudaEventRecord(eFork, 0);
    cudaStreamWaitEvent(s1, eFork, 0);

    dim3 g1(HW / OM, BHALF);
    dim3 g2(HW / MPX, BHALF);

    // default stream: batches 0..7
    offset_mma_kernel<<<g1, 256, OSMEM_TOTAL>>>(ob, 0);
    deform_mma_kernel<<<g2, 256, SMEM_TOTAL_D>>>(bias, out, 0);

    // s1: batches 8..15
    offset_mma_kernel<<<g1, 256, OSMEM_TOTAL, s1>>>(ob, BHALF);
    deform_mma_kernel<<<g2, 256, SMEM_TOTAL_D, s1>>>(bias, out, BHALF);

    // ---- join back onto default stream ----
    cudaEventRecord(eJoin, s1);
    cudaStreamWaitEvent(0, eJoin, 0);
}